// round 8
// baseline (speedup 1.0000x reference)
// mma.sync fp16 fused GEMM+epilogue, v5 = v3 mainloop + stream-K persistent CTAs.
// v3 (341.8us): 128x128 CTA tile, 8 warps of 64x32, 2 CTAs/SM, 3-stage cp.async,
// single barrier/chunk, early issue -> tensor 72.2%. Remaining loss: 1024 tiles /
// 296 resident CTAs = 3.46 waves -> 13.5% tail. v5 flattens work into 65536
// (tile,chunk) units over 2*SM persistent CTAs; pipeline runs across tile
// boundaries; split tiles (<=2 contributors) combine lock-free via workspace
// slots + per-tile atomic counter (last arriver does the fused epilogue).
//   out = relu(1 - beta + X@W^T); res = relu(1 - beta_res + x + out); leaky==id.

#include <cuda_runtime.h>
#include <cuda_fp16.h>
#include <cstdint>

#define DIM     4096
#define BK      64                     // halves per chunk = 128 bytes per row
#define STAGES  3
#define NT      256                    // 8 warps, each 64x32
#define NTILE_X 32                     // tiles per row/col (4096/128)
#define NTILES  (NTILE_X * NTILE_X)    // 1024
#define UCHUNKS 64                     // k-chunks per tile
#define U_TOTAL (NTILES * UCHUNKS)     // 65536
#define AB_TILE (128 * BK * 2)         // 16384 bytes
#define STAGE_BYTES (2 * AB_TILE)      // 32768
#define SMEM_MAIN   (STAGES * STAGE_BYTES)  // 98304
#define SMEM_TOTAL  (SMEM_MAIN + 128)       // + comm slot

// ------------------------------------------------------------------ scratch
__device__ __half g_Xh[(size_t)DIM * DIM];
__device__ __half g_Wh[(size_t)DIM * DIM];
__device__ float  g_ws[(size_t)NTILES * 2 * 64 * NT];   // [tile][slot][acc_i][tid]
__device__ int    g_cnt[NTILES];

// ------------------------------------------------------------------ helpers
__device__ __forceinline__ uint32_t smem_u32(const void* p) {
    uint32_t a;
    asm("{ .reg .u64 t; cvta.to.shared.u64 t, %1; cvt.u32.u64 %0, t; }" : "=r"(a) : "l"(p));
    return a;
}
__device__ __forceinline__ void cp16(uint32_t saddr, const void* gaddr) {
    asm volatile("cp.async.cg.shared.global [%0], [%1], 16;"
                 :: "r"(saddr), "l"(gaddr) : "memory");
}
__device__ __forceinline__ void cp_commit() {
    asm volatile("cp.async.commit_group;" ::: "memory");
}
template <int N>
__device__ __forceinline__ void cp_wait() {
    asm volatile("cp.async.wait_group %0;" :: "n"(N) : "memory");
}
__device__ __forceinline__ void ldsm4(uint32_t* r, uint32_t addr) {
    asm volatile("ldmatrix.sync.aligned.m8n8.x4.shared.b16 {%0,%1,%2,%3}, [%4];"
                 : "=r"(r[0]), "=r"(r[1]), "=r"(r[2]), "=r"(r[3]) : "r"(addr));
}
__device__ __forceinline__ void mma_f16(float* d, const uint32_t* a, const uint32_t* b) {
    asm volatile(
        "mma.sync.aligned.m16n8k16.row.col.f32.f16.f16.f32 "
        "{%0,%1,%2,%3}, {%4,%5,%6,%7}, {%8,%9}, {%0,%1,%2,%3};"
        : "+f"(d[0]), "+f"(d[1]), "+f"(d[2]), "+f"(d[3])
        : "r"(a[0]), "r"(a[1]), "r"(a[2]), "r"(a[3]), "r"(b[0]), "r"(b[1]));
}

// ------------------------------------------------------------------ prep kernel
// grid.y selects matrix; also resets the per-tile counters (first 4 x-blocks).
__global__ void __launch_bounds__(256) to_half2_kernel(const float* __restrict__ x,
                                                       const float* __restrict__ w,
                                                       __half* __restrict__ xh,
                                                       __half* __restrict__ wh) {
    if (blockIdx.y == 0 && blockIdx.x < NTILES / 256)
        g_cnt[blockIdx.x * 256 + threadIdx.x] = 0;

    const float* in  = blockIdx.y ? w : x;
    __half* outp     = blockIdx.y ? wh : xh;
    size_t i = ((size_t)blockIdx.x * blockDim.x + threadIdx.x) * 8;
    float4 v0 = *reinterpret_cast<const float4*>(in + i);
    float4 v1 = *reinterpret_cast<const float4*>(in + i + 4);
    __half2 h0 = __floats2half2_rn(v0.x, v0.y);
    __half2 h1 = __floats2half2_rn(v0.z, v0.w);
    __half2 h2 = __floats2half2_rn(v1.x, v1.y);
    __half2 h3 = __floats2half2_rn(v1.z, v1.w);
    uint4 o;
    o.x = *reinterpret_cast<uint32_t*>(&h0);
    o.y = *reinterpret_cast<uint32_t*>(&h1);
    o.z = *reinterpret_cast<uint32_t*>(&h2);
    o.w = *reinterpret_cast<uint32_t*>(&h3);
    *reinterpret_cast<uint4*>(outp + i) = o;
}

// ------------------------------------------------------------------ main kernel
__global__ void __launch_bounds__(NT, 2)
resfc_mma_f16_v5(const __half* __restrict__ Ah,
                 const __half* __restrict__ Bh,
                 const float* __restrict__ X,
                 const float* __restrict__ beta,
                 const float* __restrict__ beta_res,
                 float* __restrict__ out)
{
    extern __shared__ __align__(1024) char smem[];
    const uint32_t sbase = smem_u32(smem);
    int* comm = reinterpret_cast<int*>(smem + SMEM_MAIN);
    const int tid = threadIdx.x;
    const int l   = tid & 31;
    const int wid = tid >> 5;             // 0..7
    const int warpM = (wid & 1) * 64;     // 2 warps in M
    const int warpN = (wid >> 1) * 32;    // 4 warps in N

    // persistent work range: units u in [u0, u1), unit = tile*64 + chunk
    const int G = (int)gridDim.x;
    const int u0 = (int)(((long long)blockIdx.x * U_TOTAL) / G);
    const int u1 = (int)(((long long)(blockIdx.x + 1) * U_TOTAL) / G);

    // ---- cp.async per-thread terms
    const int grow = tid >> 3;            // row 0..31 (+32 per pass)
    const int gcol = tid & 7;             // 16B granule within 128B row
    const uint32_t swz = (uint32_t)((gcol * 16) ^ ((grow & 7) << 4));

    // ---- ldmatrix per-thread terms (SW128 swizzle within tile)
    const uint32_t xorv   = (uint32_t)(l & 7) << 4;
    const uint32_t aRow   = (uint32_t)(warpM + (l & 15));
    const uint32_t aByteH = (uint32_t)(l & 16);
    const uint32_t bRow   = (uint32_t)(warpN + (l & 7) + ((l >> 1) & 8));
    const uint32_t bByteH = (uint32_t)((l & 8) << 1);

    float acc[4][4][4];
    #pragma unroll
    for (int i = 0; i < 4; ++i)
        #pragma unroll
        for (int j = 0; j < 4; ++j)
            #pragma unroll
            for (int k = 0; k < 4; ++k)
                acc[i][j][k] = 0.0f;

    #define ISSUE_UNIT(uu, stg) do {                                          \
        const int t_ = (uu) >> 6, c_ = (uu) & 63;                             \
        const uint32_t sa_ = sbase + (uint32_t)(stg) * STAGE_BYTES;           \
        const __half* ga_ = Ah + (size_t)(((t_ >> 5) << 7) + grow) * DIM      \
                               + c_ * BK + (gcol << 3);                       \
        const __half* gb_ = Bh + (size_t)(((t_ & 31) << 7) + grow) * DIM      \
                               + c_ * BK + (gcol << 3);                       \
        _Pragma("unroll")                                                     \
        for (int p_ = 0; p_ < 4; ++p_) {                                      \
            const uint32_t so_ = (uint32_t)(grow + p_ * 32) * 128 + swz;      \
            cp16(sa_ + so_,           ga_ + (size_t)p_ * 32 * DIM);           \
            cp16(sa_ + AB_TILE + so_, gb_ + (size_t)p_ * 32 * DIM);           \
        }                                                                     \
    } while (0)

    // -------- prologue --------
    ISSUE_UNIT(u0, 0); cp_commit();
    if (u0 + 1 < u1) ISSUE_UNIT(u0 + 1, 1);
    cp_commit();

    int st = 0;
    int fragC0 = u0 & 63;
    for (int u = u0; u < u1; ++u) {
        cp_wait<1>();
        __syncthreads();

        if (u + 2 < u1) {
            int s2 = st + 2; if (s2 >= STAGES) s2 -= STAGES;
            ISSUE_UNIT(u + 2, s2);
        }
        cp_commit();

        const uint32_t aBase = sbase + (uint32_t)st * STAGE_BYTES + aRow * 128;
        const uint32_t bBase = sbase + (uint32_t)st * STAGE_BYTES + AB_TILE + bRow * 128;

        #pragma unroll
        for (int s = 0; s < 4; ++s) {
            uint32_t aF[4][4];
            uint32_t bF[4][2];
            const uint32_t aoff = ((uint32_t)(s * 32) + aByteH) ^ xorv;
            const uint32_t boff = ((uint32_t)(s * 32) + bByteH) ^ xorv;
            #pragma unroll
            for (int t = 0; t < 4; ++t)
                ldsm4(aF[t], aBase + (uint32_t)t * 2048 + aoff);
            #pragma unroll
            for (int uu = 0; uu < 2; ++uu) {
                uint32_t r[4];
                ldsm4(r, bBase + (uint32_t)uu * 2048 + boff);
                bF[2 * uu][0]     = r[0];  bF[2 * uu][1]     = r[1];
                bF[2 * uu + 1][0] = r[2];  bF[2 * uu + 1][1] = r[3];
            }
            #pragma unroll
            for (int mt = 0; mt < 4; ++mt)
                #pragma unroll
                for (int nt = 0; nt < 4; ++nt)
                    mma_f16(acc[mt][nt], aF[mt], bF[nt]);
        }

        // -------- fragment end: combine + fused epilogue --------
        if (((u & 63) == 63) || (u + 1 == u1)) {
            const int tile = u >> 6;
            const int c1   = (u & 63) + 1;
            bool do_epi = (fragC0 == 0 && c1 == 64);

            if (!do_epi) {
                const int slot = (fragC0 == 0) ? 0 : 1;
                float* wsp = g_ws + ((size_t)tile * 2 + slot) * (64 * NT) + tid;
                #pragma unroll
                for (int mt = 0; mt < 4; ++mt)
                    #pragma unroll
                    for (int nt = 0; nt < 4; ++nt)
                        #pragma unroll
                        for (int k = 0; k < 4; ++k)
                            wsp[(((mt * 4 + nt) * 4) + k) * NT] = acc[mt][nt][k];
                __threadfence();
                __syncthreads();
                if (tid == 0) comm[0] = atomicAdd(&g_cnt[tile], 1);
                __syncthreads();
                if (comm[0] == 1) {      // last arriver: combine + epilogue
                    __threadfence();
                    const float* wo = g_ws + ((size_t)tile * 2 + (1 - slot)) * (64 * NT) + tid;
                    #pragma unroll
                    for (int mt = 0; mt < 4; ++mt)
                        #pragma unroll
                        for (int nt = 0; nt < 4; ++nt)
                            #pragma unroll
                            for (int k = 0; k < 4; ++k)
                                acc[mt][nt][k] += wo[(((mt * 4 + nt) * 4) + k) * NT];
                    do_epi = true;
                }
            }

            if (do_epi) {
                const int bm = (tile >> 5) * 128;
                const int bn = (tile & 31) * 128;
                const float one_mb = 1.0f - beta[0];
                const int colB = bn + warpN + 2 * (l & 3);
                float2 br2[4];
                #pragma unroll
                for (int nt = 0; nt < 4; ++nt)
                    br2[nt] = *reinterpret_cast<const float2*>(beta_res + colB + nt * 8);
                #pragma unroll
                for (int mt = 0; mt < 4; ++mt) {
                    #pragma unroll
                    for (int h = 0; h < 2; ++h) {
                        const int row = bm + warpM + mt * 16 + (l >> 2) + h * 8;
                        const float* xr  = X   + (size_t)row * DIM + colB;
                        float*       orw = out + (size_t)row * DIM + colB;
                        #pragma unroll
                        for (int nt = 0; nt < 4; ++nt) {
                            float2 xv = *reinterpret_cast<const float2*>(xr + nt * 8);
                            const float d0 = acc[mt][nt][h * 2 + 0];
                            const float d1 = acc[mt][nt][h * 2 + 1];
                            const float o0 = fmaxf(one_mb + d0, 0.0f);
                            const float o1 = fmaxf(one_mb + d1, 0.0f);
                            const float r0 = fmaxf(1.0f - (br2[nt].x - (xv.x + o0)), 0.0f);
                            const float r1 = fmaxf(1.0f - (br2[nt].y - (xv.y + o1)), 0.0f);
                            *reinterpret_cast<float2*>(orw + nt * 8) = make_float2(r0, r1);
                        }
                    }
                }
            }

            // reset accumulator for next fragment
            #pragma unroll
            for (int mt = 0; mt < 4; ++mt)
                #pragma unroll
                for (int nt = 0; nt < 4; ++nt)
                    #pragma unroll
                    for (int k = 0; k < 4; ++k)
                        acc[mt][nt][k] = 0.0f;
            fragC0 = 0;
        }

        if (++st == STAGES) st = 0;
    }
    #undef ISSUE_UNIT
}

// ------------------------------------------------------------------ host side
extern "C" void kernel_launch(void* const* d_in, const int* in_sizes, int n_in,
                              void* d_out, int out_size)
{
    const float* X        = (const float*)d_in[0];
    const float* W        = (const float*)d_in[1];
    const float* beta     = (const float*)d_in[2];
    const float* beta_res = (const float*)d_in[3];
    float* out            = (float*)d_out;

    void *pXh = nullptr, *pWh = nullptr;
    cudaGetSymbolAddress(&pXh, g_Xh);
    cudaGetSymbolAddress(&pWh, g_Wh);

    dim3 pgrid(DIM * DIM / (256 * 8), 2);
    to_half2_kernel<<<pgrid, 256>>>(X, W, (__half*)pXh, (__half*)pWh);

    int nsm = 148;
    cudaDeviceGetAttribute(&nsm, cudaDevAttrMultiProcessorCount, 0);
    const int G = 2 * nsm;               // persistent: 2 CTAs/SM

    cudaFuncSetAttribute(resfc_mma_f16_v5,
                         cudaFuncAttributeMaxDynamicSharedMemorySize, SMEM_TOTAL);
    resfc_mma_f16_v5<<<G, NT, SMEM_TOTAL>>>((const __half*)pXh, (const __half*)pWh,
                                            X, beta, beta_res, out);
}

// round 9
// speedup vs baseline: 1.2827x; 1.2827x over previous
// mma.sync fp16 fused GEMM+epilogue, v6 = v3 hot loop (unchanged) + hybrid split-K
// wave balancing in ONE launch. v3: 128x128 tiles, 8 warps of 64x32, 2 CTAs/SM,
// 3-stage cp.async, single barrier/chunk -> 341.8us, tensor 72.2%, but 1024 tiles
// / 296 slots = 4 wave makespan (13.5% tail). v6: tiles 0..887 = 3 exact full
// waves (data-parallel, full K); tiles 888..1023 split into 2 K-halves (272
// half-duration CTAs = 0.46-wave tail). Split tiles combine lock-free (store
// partial -> fence -> atomic counter -> last arriver adds + epilogue); this code
// runs once per CTA, OUTSIDE the hot loop (R8's failure was per-chunk addressing
// overhead, not the combine).
//   out = relu(1 - beta + X@W^T); res = relu(1 - beta_res + x + out); leaky==id.

#include <cuda_runtime.h>
#include <cuda_fp16.h>
#include <cstdint>

#define DIM     4096
#define BM      128
#define BN      128
#define BK      64
#define STAGES  3
#define NT      256
#define NC      (DIM / BK)             // 64 k-chunks
#define AB_TILE (BM * BK * 2)          // 16384
#define STAGE_BYTES (2 * AB_TILE)      // 32768
#define SMEM_MAIN   (STAGES * STAGE_BYTES)  // 98304
#define SMEM_TOTAL  (SMEM_MAIN + 16)

#define FULL_TILES  888                // 3 exact waves at 296 resident CTAs
#define SPLIT_TILES 136                // remaining tiles, 2 CTAs each
#define GRID_TOTAL  (FULL_TILES + 2 * SPLIT_TILES)   // 1160

// ------------------------------------------------------------------ scratch
__device__ __half g_Xh[(size_t)DIM * DIM];
__device__ __half g_Wh[(size_t)DIM * DIM];
__device__ float  g_ws[(size_t)SPLIT_TILES * 2 * 64 * NT];  // [tile][half][i][tid]
__device__ int    g_cnt[SPLIT_TILES];

// ------------------------------------------------------------------ helpers
__device__ __forceinline__ uint32_t smem_u32(const void* p) {
    uint32_t a;
    asm("{ .reg .u64 t; cvta.to.shared.u64 t, %1; cvt.u32.u64 %0, t; }" : "=r"(a) : "l"(p));
    return a;
}
__device__ __forceinline__ void cp16(uint32_t saddr, const void* gaddr) {
    asm volatile("cp.async.cg.shared.global [%0], [%1], 16;"
                 :: "r"(saddr), "l"(gaddr) : "memory");
}
__device__ __forceinline__ void cp_commit() {
    asm volatile("cp.async.commit_group;" ::: "memory");
}
template <int N>
__device__ __forceinline__ void cp_wait() {
    asm volatile("cp.async.wait_group %0;" :: "n"(N) : "memory");
}
__device__ __forceinline__ void ldsm4(uint32_t* r, uint32_t addr) {
    asm volatile("ldmatrix.sync.aligned.m8n8.x4.shared.b16 {%0,%1,%2,%3}, [%4];"
                 : "=r"(r[0]), "=r"(r[1]), "=r"(r[2]), "=r"(r[3]) : "r"(addr));
}
__device__ __forceinline__ void mma_f16(float* d, const uint32_t* a, const uint32_t* b) {
    asm volatile(
        "mma.sync.aligned.m16n8k16.row.col.f32.f16.f16.f32 "
        "{%0,%1,%2,%3}, {%4,%5,%6,%7}, {%8,%9}, {%0,%1,%2,%3};"
        : "+f"(d[0]), "+f"(d[1]), "+f"(d[2]), "+f"(d[3])
        : "r"(a[0]), "r"(a[1]), "r"(a[2]), "r"(a[3]), "r"(b[0]), "r"(b[1]));
}

// ------------------------------------------------------------------ prep kernel
__global__ void __launch_bounds__(256) to_half2_kernel(const float* __restrict__ x,
                                                       const float* __restrict__ w,
                                                       __half* __restrict__ xh,
                                                       __half* __restrict__ wh) {
    if (blockIdx.y == 0 && blockIdx.x == 0 && threadIdx.x < SPLIT_TILES)
        g_cnt[threadIdx.x] = 0;

    const float* in  = blockIdx.y ? w : x;
    __half* outp     = blockIdx.y ? wh : xh;
    size_t i = ((size_t)blockIdx.x * blockDim.x + threadIdx.x) * 8;
    float4 v0 = *reinterpret_cast<const float4*>(in + i);
    float4 v1 = *reinterpret_cast<const float4*>(in + i + 4);
    __half2 h0 = __floats2half2_rn(v0.x, v0.y);
    __half2 h1 = __floats2half2_rn(v0.z, v0.w);
    __half2 h2 = __floats2half2_rn(v1.x, v1.y);
    __half2 h3 = __floats2half2_rn(v1.z, v1.w);
    uint4 o;
    o.x = *reinterpret_cast<uint32_t*>(&h0);
    o.y = *reinterpret_cast<uint32_t*>(&h1);
    o.z = *reinterpret_cast<uint32_t*>(&h2);
    o.w = *reinterpret_cast<uint32_t*>(&h3);
    *reinterpret_cast<uint4*>(outp + i) = o;
}

// ------------------------------------------------------------------ main kernel
__global__ void __launch_bounds__(NT, 2)
resfc_mma_f16_v6(const __half* __restrict__ Ah,
                 const __half* __restrict__ Bh,
                 const float* __restrict__ X,
                 const float* __restrict__ beta,
                 const float* __restrict__ beta_res,
                 float* __restrict__ out)
{
    extern __shared__ __align__(1024) char smem[];
    const uint32_t sbase = smem_u32(smem);
    int* comm = reinterpret_cast<int*>(smem + SMEM_MAIN);
    const int tid = threadIdx.x;
    const int l   = tid & 31;
    const int wid = tid >> 5;
    const int warpM = (wid & 1) * 64;
    const int warpN = (wid >> 1) * 32;

    // ---- work assignment (once, outside hot loop) ----
    const int bid = (int)blockIdx.x;
    int tile, c0, cN, half;
    if (bid < FULL_TILES) { tile = bid; c0 = 0; cN = NC; half = -1; }
    else {
        const int r = bid - FULL_TILES;
        tile = FULL_TILES + (r >> 1);
        half = r & 1;
        c0 = half * (NC / 2);
        cN = NC / 2;
    }
    const int bm = (tile >> 5) * BM;
    const int bn = (tile & 31) * BN;

    // ---- cp.async per-thread terms (v3-identical) ----
    const int grow = tid >> 3;
    const int gcol = tid & 7;
    const __half* gA = Ah + (size_t)(bm + grow) * DIM + gcol * 8;
    const __half* gB = Bh + (size_t)(bn + grow) * DIM + gcol * 8;
    const uint32_t scol = (uint32_t)(gcol * 16);

    // ---- ldmatrix per-thread terms (v3-identical) ----
    const uint32_t xorv   = (uint32_t)(l & 7) << 4;
    const uint32_t aRow   = (uint32_t)(warpM + (l & 15));
    const uint32_t aByteH = (uint32_t)(l & 16);
    const uint32_t bRow   = (uint32_t)(warpN + (l & 7) + ((l >> 1) & 8));
    const uint32_t bByteH = (uint32_t)((l & 8) << 1);

    float acc[4][4][4];
    #pragma unroll
    for (int i = 0; i < 4; ++i)
        #pragma unroll
        for (int j = 0; j < 4; ++j)
            #pragma unroll
            for (int k = 0; k < 4; ++k)
                acc[i][j][k] = 0.0f;

    #define ISSUE(c, stage) do {                                              \
        const uint32_t sa_ = sbase + (uint32_t)(stage) * STAGE_BYTES;         \
        const __half* ga_ = gA + (size_t)(c) * BK;                            \
        const __half* gb_ = gB + (size_t)(c) * BK;                            \
        _Pragma("unroll")                                                     \
        for (int p_ = 0; p_ < 4; ++p_) {                                      \
            const uint32_t r_  = (uint32_t)(grow + p_ * 32);                  \
            const uint32_t so_ = r_ * 128 + (scol ^ ((r_ & 7) << 4));         \
            cp16(sa_ + so_,            ga_ + (size_t)p_ * 32 * DIM);          \
            cp16(sa_ + AB_TILE + so_,  gb_ + (size_t)p_ * 32 * DIM);          \
        }                                                                     \
    } while (0)

    // -------- prologue --------
    ISSUE(c0, 0); cp_commit();
    ISSUE(c0 + 1, 1); cp_commit();

    const int cEnd = c0 + cN;
    int stage = 0;
    for (int c = c0; c < cEnd; ++c) {
        cp_wait<STAGES - 2>();
        __syncthreads();

        const int cn = c + STAGES - 1;
        if (cn < cEnd) {
            int sn = stage + STAGES - 1; if (sn >= STAGES) sn -= STAGES;
            ISSUE(cn, sn);
        }
        cp_commit();

        const uint32_t aBase = sbase + (uint32_t)stage * STAGE_BYTES + aRow * 128;
        const uint32_t bBase = sbase + (uint32_t)stage * STAGE_BYTES + AB_TILE + bRow * 128;

        #pragma unroll
        for (int s = 0; s < 4; ++s) {
            uint32_t aF[4][4];
            uint32_t bF[4][2];
            const uint32_t aoff = ((uint32_t)(s * 32) + aByteH) ^ xorv;
            const uint32_t boff = ((uint32_t)(s * 32) + bByteH) ^ xorv;
            #pragma unroll
            for (int t = 0; t < 4; ++t)
                ldsm4(aF[t], aBase + (uint32_t)t * 2048 + aoff);
            #pragma unroll
            for (int u = 0; u < 2; ++u) {
                uint32_t r[4];
                ldsm4(r, bBase + (uint32_t)u * 2048 + boff);
                bF[2 * u][0]     = r[0];  bF[2 * u][1]     = r[1];
                bF[2 * u + 1][0] = r[2];  bF[2 * u + 1][1] = r[3];
            }
            #pragma unroll
            for (int mt = 0; mt < 4; ++mt)
                #pragma unroll
                for (int nt = 0; nt < 4; ++nt)
                    mma_f16(acc[mt][nt], aF[mt], bF[nt]);
        }

        if (++stage == STAGES) stage = 0;
    }
    #undef ISSUE

    // -------- split-tile combine (runs once, 272 CTAs only) --------
    bool do_epi = (half < 0);
    if (!do_epi) {
        const int tl = tile - FULL_TILES;
        float* wsp = g_ws + ((size_t)tl * 2 + half) * (64 * NT) + tid;
        #pragma unroll
        for (int mt = 0; mt < 4; ++mt)
            #pragma unroll
            for (int nt = 0; nt < 4; ++nt)
                #pragma unroll
                for (int k = 0; k < 4; ++k)
                    wsp[(((mt * 4 + nt) * 4) + k) * NT] = acc[mt][nt][k];
        __threadfence();
        __syncthreads();
        if (tid == 0) comm[0] = atomicAdd(&g_cnt[tl], 1);
        __syncthreads();
        if (comm[0] == 1) {
            __threadfence();
            const float* wo = g_ws + ((size_t)tl * 2 + (1 - half)) * (64 * NT) + tid;
            #pragma unroll
            for (int mt = 0; mt < 4; ++mt)
                #pragma unroll
                for (int nt = 0; nt < 4; ++nt)
                    #pragma unroll
                    for (int k = 0; k < 4; ++k)
                        acc[mt][nt][k] += wo[(((mt * 4 + nt) * 4) + k) * NT];
            do_epi = true;
        }
    }

    // -------- fused epilogue --------
    if (do_epi) {
        const float one_mb = 1.0f - beta[0];
        const int colB = bn + warpN + 2 * (l & 3);

        float2 br2[4];
        #pragma unroll
        for (int nt = 0; nt < 4; ++nt)
            br2[nt] = *reinterpret_cast<const float2*>(beta_res + colB + nt * 8);

        #pragma unroll
        for (int mt = 0; mt < 4; ++mt) {
            #pragma unroll
            for (int h = 0; h < 2; ++h) {
                const int row = bm + warpM + mt * 16 + (l >> 2) + h * 8;
                const float* xr  = X   + (size_t)row * DIM + colB;
                float*       orw = out + (size_t)row * DIM + colB;
                #pragma unroll
                for (int nt = 0; nt < 4; ++nt) {
                    float2 xv = *reinterpret_cast<const float2*>(xr + nt * 8);
                    const float d0 = acc[mt][nt][h * 2 + 0];
                    const float d1 = acc[mt][nt][h * 2 + 1];
                    const float o0 = fmaxf(one_mb + d0, 0.0f);
                    const float o1 = fmaxf(one_mb + d1, 0.0f);
                    const float r0 = fmaxf(1.0f - (br2[nt].x - (xv.x + o0)), 0.0f);
                    const float r1 = fmaxf(1.0f - (br2[nt].y - (xv.y + o1)), 0.0f);
                    *reinterpret_cast<float2*>(orw + nt * 8) = make_float2(r0, r1);
                }
            }
        }
    }
}

// ------------------------------------------------------------------ host side
extern "C" void kernel_launch(void* const* d_in, const int* in_sizes, int n_in,
                              void* d_out, int out_size)
{
    const float* X        = (const float*)d_in[0];
    const float* W        = (const float*)d_in[1];
    const float* beta     = (const float*)d_in[2];
    const float* beta_res = (const float*)d_in[3];
    float* out            = (float*)d_out;

    void *pXh = nullptr, *pWh = nullptr;
    cudaGetSymbolAddress(&pXh, g_Xh);
    cudaGetSymbolAddress(&pWh, g_Wh);

    dim3 pgrid(DIM * DIM / (256 * 8), 2);
    to_half2_kernel<<<pgrid, 256>>>(X, W, (__half*)pXh, (__half*)pWh);

    cudaFuncSetAttribute(resfc_mma_f16_v6,
                         cudaFuncAttributeMaxDynamicSharedMemorySize, SMEM_TOTAL);
    resfc_mma_f16_v6<<<GRID_TOTAL, NT, SMEM_TOTAL>>>((const __half*)pXh, (const __half*)pWh,
                                                     X, beta, beta_res, out);
}

// round 10
// speedup vs baseline: 1.4009x; 1.0921x over previous
// mma.sync fp16 fused GEMM+epilogue, v7 = v3 compute (unchanged) with TMA tile
// loads replacing cp.async. Rationale: v3 is co-bound between tensor pipe and the
// smem crossbar (96KB LDSM reads + 32KB STS writes per chunk ~= HMMA time) plus
// 2048 LDGSTS instrs/chunk of issue overhead. TMA (baseline sm_90 PTX, legal on
// compute_103) moves fills onto the dedicated TMA path and collapses the loader
// to 2 instructions per chunk from one thread. SW128 TMA layout == the manual
// swizzle the ldmatrix addressing already uses, so compute is byte-identical.
//   out = relu(1 - beta + X@W^T); res = relu(1 - beta_res + x + out); leaky==id.

#include <cuda_runtime.h>
#include <cuda.h>
#include <cuda_fp16.h>
#include <cstdint>

#define DIM     4096
#define BM      128
#define BN      128
#define BK      64                     // halves per chunk = 128 bytes per row
#define STAGES  3
#define NT      256                    // 8 warps, each 64x32
#define NC      (DIM / BK)             // 64 k-chunks
#define AB_TILE (BM * BK * 2)          // 16384
#define STAGE_BYTES (2 * AB_TILE)      // 32768
#define SMEM_MAIN   (STAGES * STAGE_BYTES)  // 98304
#define SMEM_TOTAL  (SMEM_MAIN + 64)        // + 3 mbarriers

// ------------------------------------------------------------------ scratch
__device__ __half g_Xh[(size_t)DIM * DIM];
__device__ __half g_Wh[(size_t)DIM * DIM];

// ------------------------------------------------------------------ helpers
__device__ __forceinline__ uint32_t smem_u32(const void* p) {
    uint32_t a;
    asm("{ .reg .u64 t; cvta.to.shared.u64 t, %1; cvt.u32.u64 %0, t; }" : "=r"(a) : "l"(p));
    return a;
}
__device__ __forceinline__ void mbar_init(uint32_t m, uint32_t cnt) {
    asm volatile("mbarrier.init.shared.b64 [%0], %1;" :: "r"(m), "r"(cnt) : "memory");
}
__device__ __forceinline__ void mbar_expect_tx(uint32_t m, uint32_t bytes) {
    asm volatile("mbarrier.arrive.expect_tx.shared.b64 _, [%0], %1;"
                 :: "r"(m), "r"(bytes) : "memory");
}
__device__ __forceinline__ void mbar_wait(uint32_t m, uint32_t parity) {
    asm volatile(
        "{\n\t.reg .pred P;\n\t"
        "WL_%=:\n\t"
        "mbarrier.try_wait.parity.acquire.cta.shared::cta.b64 P, [%0], %1, 0x989680;\n\t"
        "@!P bra.uni WL_%=;\n\t}"
        :: "r"(m), "r"(parity) : "memory");
}
__device__ __forceinline__ void fence_async() {
    asm volatile("fence.proxy.async.shared::cta;" ::: "memory");
}
__device__ __forceinline__ void tma2d(uint32_t dst, const CUtensorMap* map,
                                      int x, int y, uint32_t bar) {
    asm volatile(
        "cp.async.bulk.tensor.2d.shared::cta.global.tile.mbarrier::complete_tx::bytes "
        "[%0], [%1, {%2, %3}], [%4];"
        :: "r"(dst), "l"(map), "r"(x), "r"(y), "r"(bar) : "memory");
}
__device__ __forceinline__ void ldsm4(uint32_t* r, uint32_t addr) {
    asm volatile("ldmatrix.sync.aligned.m8n8.x4.shared.b16 {%0,%1,%2,%3}, [%4];"
                 : "=r"(r[0]), "=r"(r[1]), "=r"(r[2]), "=r"(r[3]) : "r"(addr));
}
__device__ __forceinline__ void mma_f16(float* d, const uint32_t* a, const uint32_t* b) {
    asm volatile(
        "mma.sync.aligned.m16n8k16.row.col.f32.f16.f16.f32 "
        "{%0,%1,%2,%3}, {%4,%5,%6,%7}, {%8,%9}, {%0,%1,%2,%3};"
        : "+f"(d[0]), "+f"(d[1]), "+f"(d[2]), "+f"(d[3])
        : "r"(a[0]), "r"(a[1]), "r"(a[2]), "r"(a[3]), "r"(b[0]), "r"(b[1]));
}

// ------------------------------------------------------------------ prep kernel
__global__ void __launch_bounds__(256) to_half2_kernel(const float* __restrict__ x,
                                                       const float* __restrict__ w,
                                                       __half* __restrict__ xh,
                                                       __half* __restrict__ wh) {
    const float* in  = blockIdx.y ? w : x;
    __half* outp     = blockIdx.y ? wh : xh;
    size_t i = ((size_t)blockIdx.x * blockDim.x + threadIdx.x) * 8;
    float4 v0 = *reinterpret_cast<const float4*>(in + i);
    float4 v1 = *reinterpret_cast<const float4*>(in + i + 4);
    __half2 h0 = __floats2half2_rn(v0.x, v0.y);
    __half2 h1 = __floats2half2_rn(v0.z, v0.w);
    __half2 h2 = __floats2half2_rn(v1.x, v1.y);
    __half2 h3 = __floats2half2_rn(v1.z, v1.w);
    uint4 o;
    o.x = *reinterpret_cast<uint32_t*>(&h0);
    o.y = *reinterpret_cast<uint32_t*>(&h1);
    o.z = *reinterpret_cast<uint32_t*>(&h2);
    o.w = *reinterpret_cast<uint32_t*>(&h3);
    *reinterpret_cast<uint4*>(outp + i) = o;
}

// ------------------------------------------------------------------ main kernel
__global__ void __launch_bounds__(NT, 2)
resfc_mma_f16_v7(const __grid_constant__ CUtensorMap tmaA,
                 const __grid_constant__ CUtensorMap tmaB,
                 const float* __restrict__ X,
                 const float* __restrict__ beta,
                 const float* __restrict__ beta_res,
                 float* __restrict__ out)
{
    extern __shared__ __align__(1024) char smem[];
    const uint32_t sbase = smem_u32(smem);
    const uint32_t mbar0 = sbase + SMEM_MAIN;    // full[s] = mbar0 + 8*s
    const int tid = threadIdx.x;
    const int l   = tid & 31;
    const int wid = tid >> 5;
    const int warpM = (wid & 1) * 64;
    const int warpN = (wid >> 1) * 32;
    const int bm = blockIdx.y * BM;
    const int bn = blockIdx.x * BN;

    if (tid == 0) {
        #pragma unroll
        for (int s = 0; s < STAGES; ++s) mbar_init(mbar0 + 8 * s, 1);
    }
    __syncthreads();

    // prologue: chunks 0,1 -> stages 0,1
    if (tid == 0) {
        #pragma unroll
        for (int s = 0; s < 2; ++s) {
            mbar_expect_tx(mbar0 + 8 * s, STAGE_BYTES);
            tma2d(sbase + s * STAGE_BYTES,           &tmaA, s * BK, bm, mbar0 + 8 * s);
            tma2d(sbase + s * STAGE_BYTES + AB_TILE, &tmaB, s * BK, bn, mbar0 + 8 * s);
        }
    }

    // ---- ldmatrix per-thread terms (SW128, identical to v3) ----
    const uint32_t xorv   = (uint32_t)(l & 7) << 4;
    const uint32_t aRow   = (uint32_t)(warpM + (l & 15));
    const uint32_t aByteH = (uint32_t)(l & 16);
    const uint32_t bRow   = (uint32_t)(warpN + (l & 7) + ((l >> 1) & 8));
    const uint32_t bByteH = (uint32_t)((l & 8) << 1);

    float acc[4][4][4];
    #pragma unroll
    for (int i = 0; i < 4; ++i)
        #pragma unroll
        for (int j = 0; j < 4; ++j)
            #pragma unroll
            for (int k = 0; k < 4; ++k)
                acc[i][j][k] = 0.0f;

    unsigned phbits = 0;   // per-stage parity bits
    int stage = 0;
    for (int c = 0; c < NC; ++c) {
        const uint32_t fullb = mbar0 + 8 * stage;
        mbar_wait(fullb, (phbits >> stage) & 1u);
        phbits ^= (1u << stage);
        __syncthreads();   // all warps past chunk c-1 compute -> its stage is free

        if (tid == 0) {
            const int cn = c + STAGES - 1;
            if (cn < NC) {
                int sn = stage + STAGES - 1; if (sn >= STAGES) sn -= STAGES;
                fence_async();
                mbar_expect_tx(mbar0 + 8 * sn, STAGE_BYTES);
                tma2d(sbase + sn * STAGE_BYTES,           &tmaA, cn * BK, bm, mbar0 + 8 * sn);
                tma2d(sbase + sn * STAGE_BYTES + AB_TILE, &tmaB, cn * BK, bn, mbar0 + 8 * sn);
            }
        }

        const uint32_t aBase = sbase + (uint32_t)stage * STAGE_BYTES + aRow * 128;
        const uint32_t bBase = sbase + (uint32_t)stage * STAGE_BYTES + AB_TILE + bRow * 128;

        #pragma unroll
        for (int s = 0; s < 4; ++s) {
            uint32_t aF[4][4];
            uint32_t bF[4][2];
            const uint32_t aoff = ((uint32_t)(s * 32) + aByteH) ^ xorv;
            const uint32_t boff = ((uint32_t)(s * 32) + bByteH) ^ xorv;
            #pragma unroll
            for (int t = 0; t < 4; ++t)
                ldsm4(aF[t], aBase + (uint32_t)t * 2048 + aoff);
            #pragma unroll
            for (int u = 0; u < 2; ++u) {
                uint32_t r[4];
                ldsm4(r, bBase + (uint32_t)u * 2048 + boff);
                bF[2 * u][0]     = r[0];  bF[2 * u][1]     = r[1];
                bF[2 * u + 1][0] = r[2];  bF[2 * u + 1][1] = r[3];
            }
            #pragma unroll
            for (int mt = 0; mt < 4; ++mt)
                #pragma unroll
                for (int nt = 0; nt < 4; ++nt)
                    mma_f16(acc[mt][nt], aF[mt], bF[nt]);
        }

        if (++stage == STAGES) stage = 0;
    }

    // -------- fused epilogue (v3-identical) --------
    const float one_mb = 1.0f - beta[0];
    const int colB = bn + warpN + 2 * (l & 3);

    float2 br2[4];
    #pragma unroll
    for (int nt = 0; nt < 4; ++nt)
        br2[nt] = *reinterpret_cast<const float2*>(beta_res + colB + nt * 8);

    #pragma unroll
    for (int mt = 0; mt < 4; ++mt) {
        #pragma unroll
        for (int h = 0; h < 2; ++h) {
            const int row = bm + warpM + mt * 16 + (l >> 2) + h * 8;
            const float* xr  = X   + (size_t)row * DIM + colB;
            float*       orw = out + (size_t)row * DIM + colB;
            #pragma unroll
            for (int nt = 0; nt < 4; ++nt) {
                float2 xv = *reinterpret_cast<const float2*>(xr + nt * 8);
                const float d0 = acc[mt][nt][h * 2 + 0];
                const float d1 = acc[mt][nt][h * 2 + 1];
                const float o0 = fmaxf(one_mb + d0, 0.0f);
                const float o1 = fmaxf(one_mb + d1, 0.0f);
                const float r0 = fmaxf(1.0f - (br2[nt].x - (xv.x + o0)), 0.0f);
                const float r1 = fmaxf(1.0f - (br2[nt].y - (xv.y + o1)), 0.0f);
                *reinterpret_cast<float2*>(orw + nt * 8) = make_float2(r0, r1);
            }
        }
    }
}

// ------------------------------------------------------------------ host side
typedef CUresult (*EncodeTiledFn)(CUtensorMap*, CUtensorMapDataType, cuuint32_t, void*,
                                  const cuuint64_t*, const cuuint64_t*, const cuuint32_t*,
                                  const cuuint32_t*, CUtensorMapInterleave, CUtensorMapSwizzle,
                                  CUtensorMapL2promotion, CUtensorMapFloatOOBfill);

static void make_map(EncodeTiledFn enc, CUtensorMap* m, void* ptr) {
    cuuint64_t dims[2]    = {DIM, DIM};               // halves per row, rows
    cuuint64_t strides[1] = {(cuuint64_t)DIM * 2};
    cuuint32_t box[2]     = {BK, 128};                // 64 halves = 128B (SW128), 128 rows
    cuuint32_t es[2]      = {1, 1};
    enc(m, CU_TENSOR_MAP_DATA_TYPE_FLOAT16, 2, ptr, dims, strides, box, es,
        CU_TENSOR_MAP_INTERLEAVE_NONE, CU_TENSOR_MAP_SWIZZLE_128B,
        CU_TENSOR_MAP_L2_PROMOTION_L2_128B, CU_TENSOR_MAP_FLOAT_OOB_FILL_NONE);
}

extern "C" void kernel_launch(void* const* d_in, const int* in_sizes, int n_in,
                              void* d_out, int out_size)
{
    const float* X        = (const float*)d_in[0];
    const float* W        = (const float*)d_in[1];
    const float* beta     = (const float*)d_in[2];
    const float* beta_res = (const float*)d_in[3];
    float* out            = (float*)d_out;

    void *pXh = nullptr, *pWh = nullptr;
    cudaGetSymbolAddress(&pXh, g_Xh);
    cudaGetSymbolAddress(&pWh, g_Wh);

    dim3 pgrid(DIM * DIM / (256 * 8), 2);
    to_half2_kernel<<<pgrid, 256>>>(X, W, (__half*)pXh, (__half*)pWh);

    void* encp = nullptr;
    cudaDriverEntryPointQueryResult st;
    cudaGetDriverEntryPointByVersion("cuTensorMapEncodeTiled", &encp, 12000,
                                     cudaEnableDefault, &st);
    EncodeTiledFn enc = (EncodeTiledFn)encp;

    static CUtensorMap mapA, mapB;   // persist past graph capture
    make_map(enc, &mapA, pXh);
    make_map(enc, &mapB, pWh);

    cudaFuncSetAttribute(resfc_mma_f16_v7,
                         cudaFuncAttributeMaxDynamicSharedMemorySize, SMEM_TOTAL);
    dim3 grid(DIM / BN, DIM / BM);   // 32 x 32, plain data-parallel (v3 grid)
    resfc_mma_f16_v7<<<grid, NT, SMEM_TOTAL>>>(mapA, mapB, X, beta, beta_res, out);
}

// round 11
// speedup vs baseline: 1.4052x; 1.0031x over previous
// mma.sync fp16 fused GEMM+epilogue, v8 = v7 (TMA loads, 64x32 warp tiles,
// 2 CTAs/SM) with the next-chunk mbarrier wait HOISTED into the current chunk's
// compute: steps 0-2 -> wait(full[c+1]) (hidden behind step 3's HMMAs) ->
// step 3 -> one bar.sync -> TMA issue c+2. Removes the serialized
// try_wait+barrier pair from the top of every chunk.
//   out = relu(1 - beta + X@W^T); res = relu(1 - beta_res + x + out); leaky==id.

#include <cuda_runtime.h>
#include <cuda.h>
#include <cuda_fp16.h>
#include <cstdint>

#define DIM     4096
#define BM      128
#define BN      128
#define BK      64                     // halves per chunk = 128 bytes per row
#define STAGES  3
#define NT      256                    // 8 warps, each 64x32
#define NC      (DIM / BK)             // 64 k-chunks
#define AB_TILE (BM * BK * 2)          // 16384
#define STAGE_BYTES (2 * AB_TILE)      // 32768
#define SMEM_MAIN   (STAGES * STAGE_BYTES)  // 98304
#define SMEM_TOTAL  (SMEM_MAIN + 64)

// ------------------------------------------------------------------ scratch
__device__ __half g_Xh[(size_t)DIM * DIM];
__device__ __half g_Wh[(size_t)DIM * DIM];

// ------------------------------------------------------------------ helpers
__device__ __forceinline__ uint32_t smem_u32(const void* p) {
    uint32_t a;
    asm("{ .reg .u64 t; cvta.to.shared.u64 t, %1; cvt.u32.u64 %0, t; }" : "=r"(a) : "l"(p));
    return a;
}
__device__ __forceinline__ void mbar_init(uint32_t m, uint32_t cnt) {
    asm volatile("mbarrier.init.shared.b64 [%0], %1;" :: "r"(m), "r"(cnt) : "memory");
}
__device__ __forceinline__ void mbar_expect_tx(uint32_t m, uint32_t bytes) {
    asm volatile("mbarrier.arrive.expect_tx.shared.b64 _, [%0], %1;"
                 :: "r"(m), "r"(bytes) : "memory");
}
__device__ __forceinline__ void mbar_wait(uint32_t m, uint32_t parity) {
    asm volatile(
        "{\n\t.reg .pred P;\n\t"
        "WL_%=:\n\t"
        "mbarrier.try_wait.parity.acquire.cta.shared::cta.b64 P, [%0], %1, 0x989680;\n\t"
        "@!P bra.uni WL_%=;\n\t}"
        :: "r"(m), "r"(parity) : "memory");
}
__device__ __forceinline__ void fence_async() {
    asm volatile("fence.proxy.async.shared::cta;" ::: "memory");
}
__device__ __forceinline__ void tma2d(uint32_t dst, const CUtensorMap* map,
                                      int x, int y, uint32_t bar) {
    asm volatile(
        "cp.async.bulk.tensor.2d.shared::cta.global.tile.mbarrier::complete_tx::bytes "
        "[%0], [%1, {%2, %3}], [%4];"
        :: "r"(dst), "l"(map), "r"(x), "r"(y), "r"(bar) : "memory");
}
__device__ __forceinline__ void ldsm4(uint32_t* r, uint32_t addr) {
    asm volatile("ldmatrix.sync.aligned.m8n8.x4.shared.b16 {%0,%1,%2,%3}, [%4];"
                 : "=r"(r[0]), "=r"(r[1]), "=r"(r[2]), "=r"(r[3]) : "r"(addr));
}
__device__ __forceinline__ void mma_f16(float* d, const uint32_t* a, const uint32_t* b) {
    asm volatile(
        "mma.sync.aligned.m16n8k16.row.col.f32.f16.f16.f32 "
        "{%0,%1,%2,%3}, {%4,%5,%6,%7}, {%8,%9}, {%0,%1,%2,%3};"
        : "+f"(d[0]), "+f"(d[1]), "+f"(d[2]), "+f"(d[3])
        : "r"(a[0]), "r"(a[1]), "r"(a[2]), "r"(a[3]), "r"(b[0]), "r"(b[1]));
}

// ------------------------------------------------------------------ prep kernel
__global__ void __launch_bounds__(256) to_half2_kernel(const float* __restrict__ x,
                                                       const float* __restrict__ w,
                                                       __half* __restrict__ xh,
                                                       __half* __restrict__ wh) {
    const float* in  = blockIdx.y ? w : x;
    __half* outp     = blockIdx.y ? wh : xh;
    size_t i = ((size_t)blockIdx.x * blockDim.x + threadIdx.x) * 8;
    float4 v0 = *reinterpret_cast<const float4*>(in + i);
    float4 v1 = *reinterpret_cast<const float4*>(in + i + 4);
    __half2 h0 = __floats2half2_rn(v0.x, v0.y);
    __half2 h1 = __floats2half2_rn(v0.z, v0.w);
    __half2 h2 = __floats2half2_rn(v1.x, v1.y);
    __half2 h3 = __floats2half2_rn(v1.z, v1.w);
    uint4 o;
    o.x = *reinterpret_cast<uint32_t*>(&h0);
    o.y = *reinterpret_cast<uint32_t*>(&h1);
    o.z = *reinterpret_cast<uint32_t*>(&h2);
    o.w = *reinterpret_cast<uint32_t*>(&h3);
    *reinterpret_cast<uint4*>(outp + i) = o;
}

// ------------------------------------------------------------------ main kernel
__global__ void __launch_bounds__(NT, 2)
resfc_mma_f16_v8(const __grid_constant__ CUtensorMap tmaA,
                 const __grid_constant__ CUtensorMap tmaB,
                 const float* __restrict__ X,
                 const float* __restrict__ beta,
                 const float* __restrict__ beta_res,
                 float* __restrict__ out)
{
    extern __shared__ __align__(1024) char smem[];
    const uint32_t sbase = smem_u32(smem);
    const uint32_t mbar0 = sbase + SMEM_MAIN;    // full[s] = mbar0 + 8*s
    const int tid = threadIdx.x;
    const int l   = tid & 31;
    const int wid = tid >> 5;
    const int warpM = (wid & 1) * 64;
    const int warpN = (wid >> 1) * 32;
    const int bm = blockIdx.y * BM;
    const int bn = blockIdx.x * BN;

    if (tid == 0) {
        #pragma unroll
        for (int s = 0; s < STAGES; ++s) mbar_init(mbar0 + 8 * s, 1);
    }
    __syncthreads();

    // prologue: chunks 0,1 -> stages 0,1
    if (tid == 0) {
        #pragma unroll
        for (int s = 0; s < 2; ++s) {
            mbar_expect_tx(mbar0 + 8 * s, STAGE_BYTES);
            tma2d(sbase + s * STAGE_BYTES,           &tmaA, s * BK, bm, mbar0 + 8 * s);
            tma2d(sbase + s * STAGE_BYTES + AB_TILE, &tmaB, s * BK, bn, mbar0 + 8 * s);
        }
    }

    // ---- ldmatrix per-thread terms (SW128, identical to v7) ----
    const uint32_t xorv   = (uint32_t)(l & 7) << 4;
    const uint32_t aRow   = (uint32_t)(warpM + (l & 15));
    const uint32_t aByteH = (uint32_t)(l & 16);
    const uint32_t bRow   = (uint32_t)(warpN + (l & 7) + ((l >> 1) & 8));
    const uint32_t bByteH = (uint32_t)((l & 8) << 1);

    float acc[4][4][4];
    #pragma unroll
    for (int i = 0; i < 4; ++i)
        #pragma unroll
        for (int j = 0; j < 4; ++j)
            #pragma unroll
            for (int k = 0; k < 4; ++k)
                acc[i][j][k] = 0.0f;

    #define KSTEP(s) do {                                                     \
        uint32_t aF[4][4];                                                    \
        uint32_t bF[4][2];                                                    \
        const uint32_t aoff = ((uint32_t)((s) * 32) + aByteH) ^ xorv;         \
        const uint32_t boff = ((uint32_t)((s) * 32) + bByteH) ^ xorv;         \
        _Pragma("unroll")                                                     \
        for (int t_ = 0; t_ < 4; ++t_)                                        \
            ldsm4(aF[t_], aBase + (uint32_t)t_ * 2048 + aoff);                \
        _Pragma("unroll")                                                     \
        for (int u_ = 0; u_ < 2; ++u_) {                                      \
            uint32_t r_[4];                                                   \
            ldsm4(r_, bBase + (uint32_t)u_ * 2048 + boff);                    \
            bF[2 * u_][0]     = r_[0];  bF[2 * u_][1]     = r_[1];            \
            bF[2 * u_ + 1][0] = r_[2];  bF[2 * u_ + 1][1] = r_[3];            \
        }                                                                     \
        _Pragma("unroll")                                                     \
        for (int mt_ = 0; mt_ < 4; ++mt_)                                     \
            _Pragma("unroll")                                                 \
            for (int nt_ = 0; nt_ < 4; ++nt_)                                 \
                mma_f16(acc[mt_][nt_], aF[mt_], bF[nt_]);                     \
    } while (0)

    // wait for chunk 0 before entering the loop
    mbar_wait(mbar0, 0);
    unsigned phbits = 1u;   // stage0 parity flipped
    int stage = 0;

    for (int c = 0; c < NC; ++c) {
        const uint32_t aBase = sbase + (uint32_t)stage * STAGE_BYTES + aRow * 128;
        const uint32_t bBase = sbase + (uint32_t)stage * STAGE_BYTES + AB_TILE + bRow * 128;

        KSTEP(0);
        KSTEP(1);
        KSTEP(2);

        // hoisted wait: chunk c+1's barrier (TMA issued >=1 chunk ago);
        // hidden behind step 3's HMMAs below.
        int snext = stage + 1; if (snext == STAGES) snext = 0;
        if (c + 1 < NC) {
            mbar_wait(mbar0 + 8 * snext, (phbits >> snext) & 1u);
            phbits ^= (1u << snext);
        }

        KSTEP(3);

        __syncthreads();   // all warps done with chunk c (and a fortiori c-1)

        if (tid == 0) {
            const int cn = c + 2;
            if (cn < NC) {
                int sn = stage + 2; if (sn >= STAGES) sn -= STAGES;   // held c-1
                fence_async();
                mbar_expect_tx(mbar0 + 8 * sn, STAGE_BYTES);
                tma2d(sbase + sn * STAGE_BYTES,           &tmaA, cn * BK, bm, mbar0 + 8 * sn);
                tma2d(sbase + sn * STAGE_BYTES + AB_TILE, &tmaB, cn * BK, bn, mbar0 + 8 * sn);
            }
        }

        stage = snext;
    }
    #undef KSTEP

    // -------- fused epilogue (v7-identical) --------
    const float one_mb = 1.0f - beta[0];
    const int colB = bn + warpN + 2 * (l & 3);

    float2 br2[4];
    #pragma unroll
    for (int nt = 0; nt < 4; ++nt)
        br2[nt] = *reinterpret_cast<const float2*>(beta_res + colB + nt * 8);

    #pragma unroll
    for (int mt = 0; mt < 4; ++mt) {
        #pragma unroll
        for (int h = 0; h < 2; ++h) {
            const int row = bm + warpM + mt * 16 + (l >> 2) + h * 8;
            const float* xr  = X   + (size_t)row * DIM + colB;
            float*       orw = out + (size_t)row * DIM + colB;
            #pragma unroll
            for (int nt = 0; nt < 4; ++nt) {
                float2 xv = *reinterpret_cast<const float2*>(xr + nt * 8);
                const float d0 = acc[mt][nt][h * 2 + 0];
                const float d1 = acc[mt][nt][h * 2 + 1];
                const float o0 = fmaxf(one_mb + d0, 0.0f);
                const float o1 = fmaxf(one_mb + d1, 0.0f);
                const float r0 = fmaxf(1.0f - (br2[nt].x - (xv.x + o0)), 0.0f);
                const float r1 = fmaxf(1.0f - (br2[nt].y - (xv.y + o1)), 0.0f);
                *reinterpret_cast<float2*>(orw + nt * 8) = make_float2(r0, r1);
            }
        }
    }
}

// ------------------------------------------------------------------ host side
typedef CUresult (*EncodeTiledFn)(CUtensorMap*, CUtensorMapDataType, cuuint32_t, void*,
                                  const cuuint64_t*, const cuuint64_t*, const cuuint32_t*,
                                  const cuuint32_t*, CUtensorMapInterleave, CUtensorMapSwizzle,
                                  CUtensorMapL2promotion, CUtensorMapFloatOOBfill);

static void make_map(EncodeTiledFn enc, CUtensorMap* m, void* ptr) {
    cuuint64_t dims[2]    = {DIM, DIM};
    cuuint64_t strides[1] = {(cuuint64_t)DIM * 2};
    cuuint32_t box[2]     = {BK, 128};
    cuuint32_t es[2]      = {1, 1};
    enc(m, CU_TENSOR_MAP_DATA_TYPE_FLOAT16, 2, ptr, dims, strides, box, es,
        CU_TENSOR_MAP_INTERLEAVE_NONE, CU_TENSOR_MAP_SWIZZLE_128B,
        CU_TENSOR_MAP_L2_PROMOTION_L2_256B, CU_TENSOR_MAP_FLOAT_OOB_FILL_NONE);
}

extern "C" void kernel_launch(void* const* d_in, const int* in_sizes, int n_in,
                              void* d_out, int out_size)
{
    const float* X        = (const float*)d_in[0];
    const float* W        = (const float*)d_in[1];
    const float* beta     = (const float*)d_in[2];
    const float* beta_res = (const float*)d_in[3];
    float* out            = (float*)d_out;

    void *pXh = nullptr, *pWh = nullptr;
    cudaGetSymbolAddress(&pXh, g_Xh);
    cudaGetSymbolAddress(&pWh, g_Wh);

    dim3 pgrid(DIM * DIM / (256 * 8), 2);
    to_half2_kernel<<<pgrid, 256>>>(X, W, (__half*)pXh, (__half*)pWh);

    void* encp = nullptr;
    cudaDriverEntryPointQueryResult st;
    cudaGetDriverEntryPointByVersion("cuTensorMapEncodeTiled", &encp, 12000,
                                     cudaEnableDefault, &st);
    EncodeTiledFn enc = (EncodeTiledFn)encp;

    static CUtensorMap mapA, mapB;
    make_map(enc, &mapA, pXh);
    make_map(enc, &mapB, pWh);

    cudaFuncSetAttribute(resfc_mma_f16_v8,
                         cudaFuncAttributeMaxDynamicSharedMemorySize, SMEM_TOTAL);
    dim3 grid(DIM / BN, DIM / BM);   // 32 x 32
    resfc_mma_f16_v8<<<grid, NT, SMEM_TOTAL>>>(mapA, mapB, X, beta, beta_res, out);
}

// round 12
// speedup vs baseline: 1.4236x; 1.0131x over previous
// mma.sync fp16 fused GEMM+epilogue, v9 = v8 (TMA, 64x32 warps, 2 CTAs/SM) +
// (1) per-warp rotated k-step order -> desynchronize post-barrier LDSM bursts,
// (2) epilogue residual read from fp16 Xh (halves tail DRAM read),
// (3) prep loads with __ldcs (fp32 inputs never re-read; keep L2 clean).
//   out = relu(1 - beta + X@W^T); res = relu(1 - beta_res + x + out); leaky==id.

#include <cuda_runtime.h>
#include <cuda.h>
#include <cuda_fp16.h>
#include <cstdint>

#define DIM     4096
#define BM      128
#define BN      128
#define BK      64
#define STAGES  3
#define NT      256
#define NC      (DIM / BK)
#define AB_TILE (BM * BK * 2)
#define STAGE_BYTES (2 * AB_TILE)
#define SMEM_MAIN   (STAGES * STAGE_BYTES)
#define SMEM_TOTAL  (SMEM_MAIN + 64)

// ------------------------------------------------------------------ scratch
__device__ __half g_Xh[(size_t)DIM * DIM];
__device__ __half g_Wh[(size_t)DIM * DIM];

// ------------------------------------------------------------------ helpers
__device__ __forceinline__ uint32_t smem_u32(const void* p) {
    uint32_t a;
    asm("{ .reg .u64 t; cvta.to.shared.u64 t, %1; cvt.u32.u64 %0, t; }" : "=r"(a) : "l"(p));
    return a;
}
__device__ __forceinline__ void mbar_init(uint32_t m, uint32_t cnt) {
    asm volatile("mbarrier.init.shared.b64 [%0], %1;" :: "r"(m), "r"(cnt) : "memory");
}
__device__ __forceinline__ void mbar_expect_tx(uint32_t m, uint32_t bytes) {
    asm volatile("mbarrier.arrive.expect_tx.shared.b64 _, [%0], %1;"
                 :: "r"(m), "r"(bytes) : "memory");
}
__device__ __forceinline__ void mbar_wait(uint32_t m, uint32_t parity) {
    asm volatile(
        "{\n\t.reg .pred P;\n\t"
        "WL_%=:\n\t"
        "mbarrier.try_wait.parity.acquire.cta.shared::cta.b64 P, [%0], %1, 0x989680;\n\t"
        "@!P bra.uni WL_%=;\n\t}"
        :: "r"(m), "r"(parity) : "memory");
}
__device__ __forceinline__ void fence_async() {
    asm volatile("fence.proxy.async.shared::cta;" ::: "memory");
}
__device__ __forceinline__ void tma2d(uint32_t dst, const CUtensorMap* map,
                                      int x, int y, uint32_t bar) {
    asm volatile(
        "cp.async.bulk.tensor.2d.shared::cta.global.tile.mbarrier::complete_tx::bytes "
        "[%0], [%1, {%2, %3}], [%4];"
        :: "r"(dst), "l"(map), "r"(x), "r"(y), "r"(bar) : "memory");
}
__device__ __forceinline__ void ldsm4(uint32_t* r, uint32_t addr) {
    asm volatile("ldmatrix.sync.aligned.m8n8.x4.shared.b16 {%0,%1,%2,%3}, [%4];"
                 : "=r"(r[0]), "=r"(r[1]), "=r"(r[2]), "=r"(r[3]) : "r"(addr));
}
__device__ __forceinline__ void mma_f16(float* d, const uint32_t* a, const uint32_t* b) {
    asm volatile(
        "mma.sync.aligned.m16n8k16.row.col.f32.f16.f16.f32 "
        "{%0,%1,%2,%3}, {%4,%5,%6,%7}, {%8,%9}, {%0,%1,%2,%3};"
        : "+f"(d[0]), "+f"(d[1]), "+f"(d[2]), "+f"(d[3])
        : "r"(a[0]), "r"(a[1]), "r"(a[2]), "r"(a[3]), "r"(b[0]), "r"(b[1]));
}

// ------------------------------------------------------------------ prep kernel
__global__ void __launch_bounds__(256) to_half2_kernel(const float* __restrict__ x,
                                                       const float* __restrict__ w,
                                                       __half* __restrict__ xh,
                                                       __half* __restrict__ wh) {
    const float* in  = blockIdx.y ? w : x;
    __half* outp     = blockIdx.y ? wh : xh;
    size_t i = ((size_t)blockIdx.x * blockDim.x + threadIdx.x) * 8;
    float4 v0 = __ldcs(reinterpret_cast<const float4*>(in + i));
    float4 v1 = __ldcs(reinterpret_cast<const float4*>(in + i + 4));
    __half2 h0 = __floats2half2_rn(v0.x, v0.y);
    __half2 h1 = __floats2half2_rn(v0.z, v0.w);
    __half2 h2 = __floats2half2_rn(v1.x, v1.y);
    __half2 h3 = __floats2half2_rn(v1.z, v1.w);
    uint4 o;
    o.x = *reinterpret_cast<uint32_t*>(&h0);
    o.y = *reinterpret_cast<uint32_t*>(&h1);
    o.z = *reinterpret_cast<uint32_t*>(&h2);
    o.w = *reinterpret_cast<uint32_t*>(&h3);
    *reinterpret_cast<uint4*>(outp + i) = o;
}

// ------------------------------------------------------------------ main kernel
__global__ void __launch_bounds__(NT, 2)
resfc_mma_f16_v9(const __grid_constant__ CUtensorMap tmaA,
                 const __grid_constant__ CUtensorMap tmaB,
                 const __half* __restrict__ Xh,
                 const float* __restrict__ beta,
                 const float* __restrict__ beta_res,
                 float* __restrict__ out)
{
    extern __shared__ __align__(1024) char smem[];
    const uint32_t sbase = smem_u32(smem);
    const uint32_t mbar0 = sbase + SMEM_MAIN;
    const int tid = threadIdx.x;
    const int l   = tid & 31;
    const int wid = tid >> 5;
    const int warpM = (wid & 1) * 64;
    const int warpN = (wid >> 1) * 32;
    const int bm = blockIdx.y * BM;
    const int bn = blockIdx.x * BN;

    if (tid == 0) {
        #pragma unroll
        for (int s = 0; s < STAGES; ++s) mbar_init(mbar0 + 8 * s, 1);
    }
    __syncthreads();

    if (tid == 0) {
        #pragma unroll
        for (int s = 0; s < 2; ++s) {
            mbar_expect_tx(mbar0 + 8 * s, STAGE_BYTES);
            tma2d(sbase + s * STAGE_BYTES,           &tmaA, s * BK, bm, mbar0 + 8 * s);
            tma2d(sbase + s * STAGE_BYTES + AB_TILE, &tmaB, s * BK, bn, mbar0 + 8 * s);
        }
    }

    const uint32_t xorv   = (uint32_t)(l & 7) << 4;
    const uint32_t aRow   = (uint32_t)(warpM + (l & 15));
    const uint32_t aByteH = (uint32_t)(l & 16);
    const uint32_t bRow   = (uint32_t)(warpN + (l & 7) + ((l >> 1) & 8));
    const uint32_t bByteH = (uint32_t)((l & 8) << 1);
    const uint32_t rot    = (uint32_t)(wid & 3);   // per-warp k-step rotation

    float acc[4][4][4];
    #pragma unroll
    for (int i = 0; i < 4; ++i)
        #pragma unroll
        for (int j = 0; j < 4; ++j)
            #pragma unroll
            for (int k = 0; k < 4; ++k)
                acc[i][j][k] = 0.0f;

    #define KSTEP(srot) do {                                                  \
        const uint32_t ss_ = ((srot) + rot) & 3u;                             \
        uint32_t aF[4][4];                                                    \
        uint32_t bF[4][2];                                                    \
        const uint32_t aoff = ((ss_ * 32u) + aByteH) ^ xorv;                  \
        const uint32_t boff = ((ss_ * 32u) + bByteH) ^ xorv;                  \
        _Pragma("unroll")                                                     \
        for (int t_ = 0; t_ < 4; ++t_)                                        \
            ldsm4(aF[t_], aBase + (uint32_t)t_ * 2048 + aoff);                \
        _Pragma("unroll")                                                     \
        for (int u_ = 0; u_ < 2; ++u_) {                                      \
            uint32_t r_[4];                                                   \
            ldsm4(r_, bBase + (uint32_t)u_ * 2048 + boff);                    \
            bF[2 * u_][0]     = r_[0];  bF[2 * u_][1]     = r_[1];            \
            bF[2 * u_ + 1][0] = r_[2];  bF[2 * u_ + 1][1] = r_[3];            \
        }                                                                     \
        _Pragma("unroll")                                                     \
        for (int mt_ = 0; mt_ < 4; ++mt_)                                     \
            _Pragma("unroll")                                                 \
            for (int nt_ = 0; nt_ < 4; ++nt_)                                 \
                mma_f16(acc[mt_][nt_], aF[mt_], bF[nt_]);                     \
    } while (0)

    mbar_wait(mbar0, 0);
    unsigned phbits = 1u;
    int stage = 0;

    for (int c = 0; c < NC; ++c) {
        const uint32_t aBase = sbase + (uint32_t)stage * STAGE_BYTES + aRow * 128;
        const uint32_t bBase = sbase + (uint32_t)stage * STAGE_BYTES + AB_TILE + bRow * 128;

        KSTEP(0);
        KSTEP(1);
        KSTEP(2);

        int snext = stage + 1; if (snext == STAGES) snext = 0;
        if (c + 1 < NC) {
            mbar_wait(mbar0 + 8 * snext, (phbits >> snext) & 1u);
            phbits ^= (1u << snext);
        }

        KSTEP(3);

        __syncthreads();

        if (tid == 0) {
            const int cn = c + 2;
            if (cn < NC) {
                int sn = stage + 2; if (sn >= STAGES) sn -= STAGES;
                fence_async();
                mbar_expect_tx(mbar0 + 8 * sn, STAGE_BYTES);
                tma2d(sbase + sn * STAGE_BYTES,           &tmaA, cn * BK, bm, mbar0 + 8 * sn);
                tma2d(sbase + sn * STAGE_BYTES + AB_TILE, &tmaB, cn * BK, bn, mbar0 + 8 * sn);
            }
        }

        stage = snext;
    }
    #undef KSTEP

    // -------- fused epilogue (residual from fp16 Xh) --------
    const float one_mb = 1.0f - beta[0];
    const int colB = bn + warpN + 2 * (l & 3);

    float2 br2[4];
    #pragma unroll
    for (int nt = 0; nt < 4; ++nt)
        br2[nt] = *reinterpret_cast<const float2*>(beta_res + colB + nt * 8);

    #pragma unroll
    for (int mt = 0; mt < 4; ++mt) {
        #pragma unroll
        for (int h = 0; h < 2; ++h) {
            const int row = bm + warpM + mt * 16 + (l >> 2) + h * 8;
            const __half* xr = Xh  + (size_t)row * DIM + colB;
            float*       orw = out + (size_t)row * DIM + colB;
            #pragma unroll
            for (int nt = 0; nt < 4; ++nt) {
                const __half2 xh2 = *reinterpret_cast<const __half2*>(xr + nt * 8);
                const float2 xv = __half22float2(xh2);
                const float d0 = acc[mt][nt][h * 2 + 0];
                const float d1 = acc[mt][nt][h * 2 + 1];
                const float o0 = fmaxf(one_mb + d0, 0.0f);
                const float o1 = fmaxf(one_mb + d1, 0.0f);
                const float r0 = fmaxf(1.0f - (br2[nt].x - (xv.x + o0)), 0.0f);
                const float r1 = fmaxf(1.0f - (br2[nt].y - (xv.y + o1)), 0.0f);
                *reinterpret_cast<float2*>(orw + nt * 8) = make_float2(r0, r1);
            }
        }
    }
}

// ------------------------------------------------------------------ host side
typedef CUresult (*EncodeTiledFn)(CUtensorMap*, CUtensorMapDataType, cuuint32_t, void*,
                                  const cuuint64_t*, const cuuint64_t*, const cuuint32_t*,
                                  const cuuint32_t*, CUtensorMapInterleave, CUtensorMapSwizzle,
                                  CUtensorMapL2promotion, CUtensorMapFloatOOBfill);

static void make_map(EncodeTiledFn enc, CUtensorMap* m, void* ptr) {
    cuuint64_t dims[2]    = {DIM, DIM};
    cuuint64_t strides[1] = {(cuuint64_t)DIM * 2};
    cuuint32_t box[2]     = {BK, 128};
    cuuint32_t es[2]      = {1, 1};
    enc(m, CU_TENSOR_MAP_DATA_TYPE_FLOAT16, 2, ptr, dims, strides, box, es,
        CU_TENSOR_MAP_INTERLEAVE_NONE, CU_TENSOR_MAP_SWIZZLE_128B,
        CU_TENSOR_MAP_L2_PROMOTION_L2_256B, CU_TENSOR_MAP_FLOAT_OOB_FILL_NONE);
}

extern "C" void kernel_launch(void* const* d_in, const int* in_sizes, int n_in,
                              void* d_out, int out_size)
{
    const float* X        = (const float*)d_in[0];
    const float* W        = (const float*)d_in[1];
    const float* beta     = (const float*)d_in[2];
    const float* beta_res = (const float*)d_in[3];
    float* out            = (float*)d_out;

    void *pXh = nullptr, *pWh = nullptr;
    cudaGetSymbolAddress(&pXh, g_Xh);
    cudaGetSymbolAddress(&pWh, g_Wh);

    dim3 pgrid(DIM * DIM / (256 * 8), 2);
    to_half2_kernel<<<pgrid, 256>>>(X, W, (__half*)pXh, (__half*)pWh);

    void* encp = nullptr;
    cudaDriverEntryPointQueryResult st;
    cudaGetDriverEntryPointByVersion("cuTensorMapEncodeTiled", &encp, 12000,
                                     cudaEnableDefault, &st);
    EncodeTiledFn enc = (EncodeTiledFn)encp;

    static CUtensorMap mapA, mapB;
    make_map(enc, &mapA, pXh);
    make_map(enc, &mapB, pWh);

    cudaFuncSetAttribute(resfc_mma_f16_v9,
                         cudaFuncAttributeMaxDynamicSharedMemorySize, SMEM_TOTAL);
    dim3 grid(DIM / BN, DIM / BM);
    resfc_mma_f16_v9<<<grid, NT, SMEM_TOTAL>>>(mapA, mapB, (const __half*)pXh,
                                               beta, beta_res, out);
}

// round 13
// speedup vs baseline: 1.4702x; 1.0328x over previous
// mma.sync fp16 fused GEMM+epilogue, v10 = v9 with the mainloop made fully
// barrier-free: per-stage "empty" mbarriers (arrive-count 8, one per warp)
// replace the per-chunk __syncthreads(). Warps proceed producer/consumer style
// with bounded 3-chunk skew; tid0 issues chunk c+3's TMA after empty[c%3]
// completes. Removes 64 bar.syncs + reconvergence skew per CTA.
//   out = relu(1 - beta + X@W^T); res = relu(1 - beta_res + x + out); leaky==id.

#include <cuda_runtime.h>
#include <cuda.h>
#include <cuda_fp16.h>
#include <cstdint>

#define DIM     4096
#define BM      128
#define BN      128
#define BK      64
#define STAGES  3
#define NT      256
#define NC      (DIM / BK)
#define AB_TILE (BM * BK * 2)
#define STAGE_BYTES (2 * AB_TILE)
#define SMEM_MAIN   (STAGES * STAGE_BYTES)
#define SMEM_TOTAL  (SMEM_MAIN + 64)       // full[0..2] @ +0, empty[0..2] @ +24

// ------------------------------------------------------------------ scratch
__device__ __half g_Xh[(size_t)DIM * DIM];
__device__ __half g_Wh[(size_t)DIM * DIM];

// ------------------------------------------------------------------ helpers
__device__ __forceinline__ uint32_t smem_u32(const void* p) {
    uint32_t a;
    asm("{ .reg .u64 t; cvta.to.shared.u64 t, %1; cvt.u32.u64 %0, t; }" : "=r"(a) : "l"(p));
    return a;
}
__device__ __forceinline__ void mbar_init(uint32_t m, uint32_t cnt) {
    asm volatile("mbarrier.init.shared.b64 [%0], %1;" :: "r"(m), "r"(cnt) : "memory");
}
__device__ __forceinline__ void mbar_arrive(uint32_t m) {
    asm volatile("mbarrier.arrive.shared.b64 _, [%0];" :: "r"(m) : "memory");
}
__device__ __forceinline__ void mbar_expect_tx(uint32_t m, uint32_t bytes) {
    asm volatile("mbarrier.arrive.expect_tx.shared.b64 _, [%0], %1;"
                 :: "r"(m), "r"(bytes) : "memory");
}
__device__ __forceinline__ void mbar_wait(uint32_t m, uint32_t parity) {
    asm volatile(
        "{\n\t.reg .pred P;\n\t"
        "WL_%=:\n\t"
        "mbarrier.try_wait.parity.acquire.cta.shared::cta.b64 P, [%0], %1, 0x989680;\n\t"
        "@!P bra.uni WL_%=;\n\t}"
        :: "r"(m), "r"(parity) : "memory");
}
__device__ __forceinline__ void fence_async() {
    asm volatile("fence.proxy.async.shared::cta;" ::: "memory");
}
__device__ __forceinline__ void tma2d(uint32_t dst, const CUtensorMap* map,
                                      int x, int y, uint32_t bar) {
    asm volatile(
        "cp.async.bulk.tensor.2d.shared::cta.global.tile.mbarrier::complete_tx::bytes "
        "[%0], [%1, {%2, %3}], [%4];"
        :: "r"(dst), "l"(map), "r"(x), "r"(y), "r"(bar) : "memory");
}
__device__ __forceinline__ void ldsm4(uint32_t* r, uint32_t addr) {
    asm volatile("ldmatrix.sync.aligned.m8n8.x4.shared.b16 {%0,%1,%2,%3}, [%4];"
                 : "=r"(r[0]), "=r"(r[1]), "=r"(r[2]), "=r"(r[3]) : "r"(addr));
}
__device__ __forceinline__ void mma_f16(float* d, const uint32_t* a, const uint32_t* b) {
    asm volatile(
        "mma.sync.aligned.m16n8k16.row.col.f32.f16.f16.f32 "
        "{%0,%1,%2,%3}, {%4,%5,%6,%7}, {%8,%9}, {%0,%1,%2,%3};"
        : "+f"(d[0]), "+f"(d[1]), "+f"(d[2]), "+f"(d[3])
        : "r"(a[0]), "r"(a[1]), "r"(a[2]), "r"(a[3]), "r"(b[0]), "r"(b[1]));
}

// ------------------------------------------------------------------ prep kernel
__global__ void __launch_bounds__(256) to_half2_kernel(const float* __restrict__ x,
                                                       const float* __restrict__ w,
                                                       __half* __restrict__ xh,
                                                       __half* __restrict__ wh) {
    const float* in  = blockIdx.y ? w : x;
    __half* outp     = blockIdx.y ? wh : xh;
    size_t i = ((size_t)blockIdx.x * blockDim.x + threadIdx.x) * 8;
    float4 v0 = __ldcs(reinterpret_cast<const float4*>(in + i));
    float4 v1 = __ldcs(reinterpret_cast<const float4*>(in + i + 4));
    __half2 h0 = __floats2half2_rn(v0.x, v0.y);
    __half2 h1 = __floats2half2_rn(v0.z, v0.w);
    __half2 h2 = __floats2half2_rn(v1.x, v1.y);
    __half2 h3 = __floats2half2_rn(v1.z, v1.w);
    uint4 o;
    o.x = *reinterpret_cast<uint32_t*>(&h0);
    o.y = *reinterpret_cast<uint32_t*>(&h1);
    o.z = *reinterpret_cast<uint32_t*>(&h2);
    o.w = *reinterpret_cast<uint32_t*>(&h3);
    *reinterpret_cast<uint4*>(outp + i) = o;
}

// ------------------------------------------------------------------ main kernel
__global__ void __launch_bounds__(NT, 2)
resfc_mma_f16_v10(const __grid_constant__ CUtensorMap tmaA,
                  const __grid_constant__ CUtensorMap tmaB,
                  const __half* __restrict__ Xh,
                  const float* __restrict__ beta,
                  const float* __restrict__ beta_res,
                  float* __restrict__ out)
{
    extern __shared__ __align__(1024) char smem[];
    const uint32_t sbase = smem_u32(smem);
    const uint32_t fullb0  = sbase + SMEM_MAIN;        // 8B each
    const uint32_t emptyb0 = sbase + SMEM_MAIN + 24;
    const int tid = threadIdx.x;
    const int l   = tid & 31;
    const int wid = tid >> 5;
    const int warpM = (wid & 1) * 64;
    const int warpN = (wid >> 1) * 32;
    const int bm = blockIdx.y * BM;
    const int bn = blockIdx.x * BN;

    if (tid == 0) {
        #pragma unroll
        for (int s = 0; s < STAGES; ++s) {
            mbar_init(fullb0  + 8 * s, 1);
            mbar_init(emptyb0 + 8 * s, 8);   // one arrive per warp
        }
    }
    __syncthreads();

    // prologue: chunks 0,1,2 -> stages 0,1,2 (all empty at start)
    if (tid == 0) {
        #pragma unroll
        for (int s = 0; s < STAGES; ++s) {
            mbar_expect_tx(fullb0 + 8 * s, STAGE_BYTES);
            tma2d(sbase + s * STAGE_BYTES,           &tmaA, s * BK, bm, fullb0 + 8 * s);
            tma2d(sbase + s * STAGE_BYTES + AB_TILE, &tmaB, s * BK, bn, fullb0 + 8 * s);
        }
    }

    const uint32_t xorv   = (uint32_t)(l & 7) << 4;
    const uint32_t aRow   = (uint32_t)(warpM + (l & 15));
    const uint32_t aByteH = (uint32_t)(l & 16);
    const uint32_t bRow   = (uint32_t)(warpN + (l & 7) + ((l >> 1) & 8));
    const uint32_t bByteH = (uint32_t)((l & 8) << 1);
    const uint32_t rot    = (uint32_t)(wid & 3);

    float acc[4][4][4];
    #pragma unroll
    for (int i = 0; i < 4; ++i)
        #pragma unroll
        for (int j = 0; j < 4; ++j)
            #pragma unroll
            for (int k = 0; k < 4; ++k)
                acc[i][j][k] = 0.0f;

    #define KSTEP(srot) do {                                                  \
        const uint32_t ss_ = ((srot) + rot) & 3u;                             \
        uint32_t aF[4][4];                                                    \
        uint32_t bF[4][2];                                                    \
        const uint32_t aoff = ((ss_ * 32u) + aByteH) ^ xorv;                  \
        const uint32_t boff = ((ss_ * 32u) + bByteH) ^ xorv;                  \
        _Pragma("unroll")                                                     \
        for (int t_ = 0; t_ < 4; ++t_)                                        \
            ldsm4(aF[t_], aBase + (uint32_t)t_ * 2048 + aoff);                \
        _Pragma("unroll")                                                     \
        for (int u_ = 0; u_ < 2; ++u_) {                                      \
            uint32_t r_[4];                                                   \
            ldsm4(r_, bBase + (uint32_t)u_ * 2048 + boff);                    \
            bF[2 * u_][0]     = r_[0];  bF[2 * u_][1]     = r_[1];            \
            bF[2 * u_ + 1][0] = r_[2];  bF[2 * u_ + 1][1] = r_[3];            \
        }                                                                     \
        _Pragma("unroll")                                                     \
        for (int mt_ = 0; mt_ < 4; ++mt_)                                     \
            _Pragma("unroll")                                                 \
            for (int nt_ = 0; nt_ < 4; ++nt_)                                 \
                mma_f16(acc[mt_][nt_], aF[mt_], bF[nt_]);                     \
    } while (0)

    // wait for chunk 0 (stage 0)
    mbar_wait(fullb0, 0);
    unsigned phbits = 1u;      // full-barrier parities (per warp)
    unsigned eph    = 0u;      // empty-barrier parities (tid0 only)
    int stage = 0;

    for (int c = 0; c < NC; ++c) {
        const uint32_t aBase = sbase + (uint32_t)stage * STAGE_BYTES + aRow * 128;
        const uint32_t bBase = sbase + (uint32_t)stage * STAGE_BYTES + AB_TILE + bRow * 128;

        KSTEP(0);
        KSTEP(1);
        KSTEP(2);

        int snext = stage + 1; if (snext == STAGES) snext = 0;
        if (c + 1 < NC) {
            mbar_wait(fullb0 + 8 * snext, (phbits >> snext) & 1u);
            phbits ^= (1u << snext);
        }

        KSTEP(3);

        // this warp is done with chunk c / stage: publish to empty[stage]
        __syncwarp();
        if (l == 0) mbar_arrive(emptyb0 + 8 * stage);

        // producer: refill this stage with chunk c+3 once ALL warps are done
        if (tid == 0) {
            const int cn = c + STAGES;
            if (cn < NC) {
                mbar_wait(emptyb0 + 8 * stage, (eph >> stage) & 1u);
                eph ^= (1u << stage);
                fence_async();
                mbar_expect_tx(fullb0 + 8 * stage, STAGE_BYTES);
                tma2d(sbase + stage * STAGE_BYTES,           &tmaA, cn * BK, bm, fullb0 + 8 * stage);
                tma2d(sbase + stage * STAGE_BYTES + AB_TILE, &tmaB, cn * BK, bn, fullb0 + 8 * stage);
            }
        }

        stage = snext;
    }
    #undef KSTEP

    // -------- fused epilogue (residual from fp16 Xh) --------
    const float one_mb = 1.0f - beta[0];
    const int colB = bn + warpN + 2 * (l & 3);

    float2 br2[4];
    #pragma unroll
    for (int nt = 0; nt < 4; ++nt)
        br2[nt] = *reinterpret_cast<const float2*>(beta_res + colB + nt * 8);

    #pragma unroll
    for (int mt = 0; mt < 4; ++mt) {
        #pragma unroll
        for (int h = 0; h < 2; ++h) {
            const int row = bm + warpM + mt * 16 + (l >> 2) + h * 8;
            const __half* xr = Xh  + (size_t)row * DIM + colB;
            float*       orw = out + (size_t)row * DIM + colB;
            #pragma unroll
            for (int nt = 0; nt < 4; ++nt) {
                const __half2 xh2 = *reinterpret_cast<const __half2*>(xr + nt * 8);
                const float2 xv = __half22float2(xh2);
                const float d0 = acc[mt][nt][h * 2 + 0];
                const float d1 = acc[mt][nt][h * 2 + 1];
                const float o0 = fmaxf(one_mb + d0, 0.0f);
                const float o1 = fmaxf(one_mb + d1, 0.0f);
                const float r0 = fmaxf(1.0f - (br2[nt].x - (xv.x + o0)), 0.0f);
                const float r1 = fmaxf(1.0f - (br2[nt].y - (xv.y + o1)), 0.0f);
                *reinterpret_cast<float2*>(orw + nt * 8) = make_float2(r0, r1);
            }
        }
    }
}

// ------------------------------------------------------------------ host side
typedef CUresult (*EncodeTiledFn)(CUtensorMap*, CUtensorMapDataType, cuuint32_t, void*,
                                  const cuuint64_t*, const cuuint64_t*, const cuuint32_t*,
                                  const cuuint32_t*, CUtensorMapInterleave, CUtensorMapSwizzle,
                                  CUtensorMapL2promotion, CUtensorMapFloatOOBfill);

static void make_map(EncodeTiledFn enc, CUtensorMap* m, void* ptr) {
    cuuint64_t dims[2]    = {DIM, DIM};
    cuuint64_t strides[1] = {(cuuint64_t)DIM * 2};
    cuuint32_t box[2]     = {BK, 128};
    cuuint32_t es[2]      = {1, 1};
    enc(m, CU_TENSOR_MAP_DATA_TYPE_FLOAT16, 2, ptr, dims, strides, box, es,
        CU_TENSOR_MAP_INTERLEAVE_NONE, CU_TENSOR_MAP_SWIZZLE_128B,
        CU_TENSOR_MAP_L2_PROMOTION_L2_256B, CU_TENSOR_MAP_FLOAT_OOB_FILL_NONE);
}

extern "C" void kernel_launch(void* const* d_in, const int* in_sizes, int n_in,
                              void* d_out, int out_size)
{
    const float* X        = (const float*)d_in[0];
    const float* W        = (const float*)d_in[1];
    const float* beta     = (const float*)d_in[2];
    const float* beta_res = (const float*)d_in[3];
    float* out            = (float*)d_out;

    void *pXh = nullptr, *pWh = nullptr;
    cudaGetSymbolAddress(&pXh, g_Xh);
    cudaGetSymbolAddress(&pWh, g_Wh);

    dim3 pgrid(DIM * DIM / (256 * 8), 2);
    to_half2_kernel<<<pgrid, 256>>>(X, W, (__half*)pXh, (__half*)pWh);

    void* encp = nullptr;
    cudaDriverEntryPointQueryResult st;
    cudaGetDriverEntryPointByVersion("cuTensorMapEncodeTiled", &encp, 12000,
                                     cudaEnableDefault, &st);
    EncodeTiledFn enc = (EncodeTiledFn)encp;

    static CUtensorMap mapA, mapB;
    make_map(enc, &mapA, pXh);
    make_map(enc, &mapB, pWh);

    cudaFuncSetAttribute(resfc_mma_f16_v10,
                         cudaFuncAttributeMaxDynamicSharedMemorySize, SMEM_TOTAL);
    dim3 grid(DIM / BN, DIM / BM);
    resfc_mma_f16_v10<<<grid, NT, SMEM_TOTAL>>>(mapA, mapB, (const __half*)pXh,
                                                beta, beta_res, out);
}

// round 14
// speedup vs baseline: 1.4735x; 1.0022x over previous
// mma.sync fp16 fused GEMM+epilogue, v11 = v10 (barrier-free mbarrier pipeline,
// TMA loads, 64x32 warps, 2 CTAs/SM) with: producer role moved to warp 7 (the
// statistically-last arriver; frees warp 0 from the per-chunk empty-wait),
// k-step rotation removed (constant offsets; natural warp skew now provides the
// desync), and evict-first (__stcs) epilogue stores to keep L2 for Xh/Wh.
//   out = relu(1 - beta + X@W^T); res = relu(1 - beta_res + x + out); leaky==id.

#include <cuda_runtime.h>
#include <cuda.h>
#include <cuda_fp16.h>
#include <cstdint>

#define DIM     4096
#define BM      128
#define BN      128
#define BK      64
#define STAGES  3
#define NT      256
#define NC      (DIM / BK)
#define AB_TILE (BM * BK * 2)
#define STAGE_BYTES (2 * AB_TILE)
#define SMEM_MAIN   (STAGES * STAGE_BYTES)
#define SMEM_TOTAL  (SMEM_MAIN + 64)       // full[0..2] @ +0, empty[0..2] @ +24

// ------------------------------------------------------------------ scratch
__device__ __half g_Xh[(size_t)DIM * DIM];
__device__ __half g_Wh[(size_t)DIM * DIM];

// ------------------------------------------------------------------ helpers
__device__ __forceinline__ uint32_t smem_u32(const void* p) {
    uint32_t a;
    asm("{ .reg .u64 t; cvta.to.shared.u64 t, %1; cvt.u32.u64 %0, t; }" : "=r"(a) : "l"(p));
    return a;
}
__device__ __forceinline__ void mbar_init(uint32_t m, uint32_t cnt) {
    asm volatile("mbarrier.init.shared.b64 [%0], %1;" :: "r"(m), "r"(cnt) : "memory");
}
__device__ __forceinline__ void mbar_arrive(uint32_t m) {
    asm volatile("mbarrier.arrive.shared.b64 _, [%0];" :: "r"(m) : "memory");
}
__device__ __forceinline__ void mbar_expect_tx(uint32_t m, uint32_t bytes) {
    asm volatile("mbarrier.arrive.expect_tx.shared.b64 _, [%0], %1;"
                 :: "r"(m), "r"(bytes) : "memory");
}
__device__ __forceinline__ void mbar_wait(uint32_t m, uint32_t parity) {
    asm volatile(
        "{\n\t.reg .pred P;\n\t"
        "WL_%=:\n\t"
        "mbarrier.try_wait.parity.acquire.cta.shared::cta.b64 P, [%0], %1, 0x989680;\n\t"
        "@!P bra.uni WL_%=;\n\t}"
        :: "r"(m), "r"(parity) : "memory");
}
__device__ __forceinline__ void fence_async() {
    asm volatile("fence.proxy.async.shared::cta;" ::: "memory");
}
__device__ __forceinline__ void tma2d(uint32_t dst, const CUtensorMap* map,
                                      int x, int y, uint32_t bar) {
    asm volatile(
        "cp.async.bulk.tensor.2d.shared::cta.global.tile.mbarrier::complete_tx::bytes "
        "[%0], [%1, {%2, %3}], [%4];"
        :: "r"(dst), "l"(map), "r"(x), "r"(y), "r"(bar) : "memory");
}
__device__ __forceinline__ void ldsm4(uint32_t* r, uint32_t addr) {
    asm volatile("ldmatrix.sync.aligned.m8n8.x4.shared.b16 {%0,%1,%2,%3}, [%4];"
                 : "=r"(r[0]), "=r"(r[1]), "=r"(r[2]), "=r"(r[3]) : "r"(addr));
}
__device__ __forceinline__ void mma_f16(float* d, const uint32_t* a, const uint32_t* b) {
    asm volatile(
        "mma.sync.aligned.m16n8k16.row.col.f32.f16.f16.f32 "
        "{%0,%1,%2,%3}, {%4,%5,%6,%7}, {%8,%9}, {%0,%1,%2,%3};"
        : "+f"(d[0]), "+f"(d[1]), "+f"(d[2]), "+f"(d[3])
        : "r"(a[0]), "r"(a[1]), "r"(a[2]), "r"(a[3]), "r"(b[0]), "r"(b[1]));
}

// ------------------------------------------------------------------ prep kernel
__global__ void __launch_bounds__(256) to_half2_kernel(const float* __restrict__ x,
                                                       const float* __restrict__ w,
                                                       __half* __restrict__ xh,
                                                       __half* __restrict__ wh) {
    const float* in  = blockIdx.y ? w : x;
    __half* outp     = blockIdx.y ? wh : xh;
    size_t i = ((size_t)blockIdx.x * blockDim.x + threadIdx.x) * 8;
    float4 v0 = __ldcs(reinterpret_cast<const float4*>(in + i));
    float4 v1 = __ldcs(reinterpret_cast<const float4*>(in + i + 4));
    __half2 h0 = __floats2half2_rn(v0.x, v0.y);
    __half2 h1 = __floats2half2_rn(v0.z, v0.w);
    __half2 h2 = __floats2half2_rn(v1.x, v1.y);
    __half2 h3 = __floats2half2_rn(v1.z, v1.w);
    uint4 o;
    o.x = *reinterpret_cast<uint32_t*>(&h0);
    o.y = *reinterpret_cast<uint32_t*>(&h1);
    o.z = *reinterpret_cast<uint32_t*>(&h2);
    o.w = *reinterpret_cast<uint32_t*>(&h3);
    *reinterpret_cast<uint4*>(outp + i) = o;
}

// ------------------------------------------------------------------ main kernel
__global__ void __launch_bounds__(NT, 2)
resfc_mma_f16_v11(const __grid_constant__ CUtensorMap tmaA,
                  const __grid_constant__ CUtensorMap tmaB,
                  const __half* __restrict__ Xh,
                  const float* __restrict__ beta,
                  const float* __restrict__ beta_res,
                  float* __restrict__ out)
{
    extern __shared__ __align__(1024) char smem[];
    const uint32_t sbase = smem_u32(smem);
    const uint32_t fullb0  = sbase + SMEM_MAIN;
    const uint32_t emptyb0 = sbase + SMEM_MAIN + 24;
    const int tid = threadIdx.x;
    const int l   = tid & 31;
    const int wid = tid >> 5;
    const int warpM = (wid & 1) * 64;
    const int warpN = (wid >> 1) * 32;
    const int bm = blockIdx.y * BM;
    const int bn = blockIdx.x * BN;

    if (tid == 0) {
        #pragma unroll
        for (int s = 0; s < STAGES; ++s) {
            mbar_init(fullb0  + 8 * s, 1);
            mbar_init(emptyb0 + 8 * s, 8);
        }
    }
    __syncthreads();

    // prologue: chunks 0,1,2 -> stages 0,1,2
    if (tid == 0) {
        #pragma unroll
        for (int s = 0; s < STAGES; ++s) {
            mbar_expect_tx(fullb0 + 8 * s, STAGE_BYTES);
            tma2d(sbase + s * STAGE_BYTES,           &tmaA, s * BK, bm, fullb0 + 8 * s);
            tma2d(sbase + s * STAGE_BYTES + AB_TILE, &tmaB, s * BK, bn, fullb0 + 8 * s);
        }
    }

    const uint32_t xorv   = (uint32_t)(l & 7) << 4;
    const uint32_t aRow   = (uint32_t)(warpM + (l & 15));
    const uint32_t aByteH = (uint32_t)(l & 16);
    const uint32_t bRow   = (uint32_t)(warpN + (l & 7) + ((l >> 1) & 8));
    const uint32_t bByteH = (uint32_t)((l & 8) << 1);

    float acc[4][4][4];
    #pragma unroll
    for (int i = 0; i < 4; ++i)
        #pragma unroll
        for (int j = 0; j < 4; ++j)
            #pragma unroll
            for (int k = 0; k < 4; ++k)
                acc[i][j][k] = 0.0f;

    #define KSTEP(s) do {                                                     \
        uint32_t aF[4][4];                                                    \
        uint32_t bF[4][2];                                                    \
        const uint32_t aoff = ((uint32_t)((s) * 32) + aByteH) ^ xorv;         \
        const uint32_t boff = ((uint32_t)((s) * 32) + bByteH) ^ xorv;         \
        _Pragma("unroll")                                                     \
        for (int t_ = 0; t_ < 4; ++t_)                                        \
            ldsm4(aF[t_], aBase + (uint32_t)t_ * 2048 + aoff);                \
        _Pragma("unroll")                                                     \
        for (int u_ = 0; u_ < 2; ++u_) {                                      \
            uint32_t r_[4];                                                   \
            ldsm4(r_, bBase + (uint32_t)u_ * 2048 + boff);                    \
            bF[2 * u_][0]     = r_[0];  bF[2 * u_][1]     = r_[1];            \
            bF[2 * u_ + 1][0] = r_[2];  bF[2 * u_ + 1][1] = r_[3];            \
        }                                                                     \
        _Pragma("unroll")                                                     \
        for (int mt_ = 0; mt_ < 4; ++mt_)                                     \
            _Pragma("unroll")                                                 \
            for (int nt_ = 0; nt_ < 4; ++nt_)                                 \
                mma_f16(acc[mt_][nt_], aF[mt_], bF[nt_]);                     \
    } while (0)

    mbar_wait(fullb0, 0);
    unsigned phbits = 1u;
    unsigned eph    = 0u;      // producer-thread parity bits (tid 224)
    int stage = 0;

    for (int c = 0; c < NC; ++c) {
        const uint32_t aBase = sbase + (uint32_t)stage * STAGE_BYTES + aRow * 128;
        const uint32_t bBase = sbase + (uint32_t)stage * STAGE_BYTES + AB_TILE + bRow * 128;

        KSTEP(0);
        KSTEP(1);
        KSTEP(2);

        int snext = stage + 1; if (snext == STAGES) snext = 0;
        if (c + 1 < NC) {
            mbar_wait(fullb0 + 8 * snext, (phbits >> snext) & 1u);
            phbits ^= (1u << snext);
        }

        KSTEP(3);

        __syncwarp();
        if (l == 0) mbar_arrive(emptyb0 + 8 * stage);

        // producer = warp 7 lane 0 (statistically last arriver; warp 0 freed)
        if (tid == 224) {
            const int cn = c + STAGES;
            if (cn < NC) {
                mbar_wait(emptyb0 + 8 * stage, (eph >> stage) & 1u);
                eph ^= (1u << stage);
                fence_async();
                mbar_expect_tx(fullb0 + 8 * stage, STAGE_BYTES);
                tma2d(sbase + stage * STAGE_BYTES,           &tmaA, cn * BK, bm, fullb0 + 8 * stage);
                tma2d(sbase + stage * STAGE_BYTES + AB_TILE, &tmaB, cn * BK, bn, fullb0 + 8 * stage);
            }
        }

        stage = snext;
    }
    #undef KSTEP

    // -------- fused epilogue (residual from fp16 Xh; evict-first stores) -----
    const float one_mb = 1.0f - beta[0];
    const int colB = bn + warpN + 2 * (l & 3);

    float2 br2[4];
    #pragma unroll
    for (int nt = 0; nt < 4; ++nt)
        br2[nt] = *reinterpret_cast<const float2*>(beta_res + colB + nt * 8);

    #pragma unroll
    for (int mt = 0; mt < 4; ++mt) {
        #pragma unroll
        for (int h = 0; h < 2; ++h) {
            const int row = bm + warpM + mt * 16 + (l >> 2) + h * 8;
            const __half* xr = Xh  + (size_t)row * DIM + colB;
            float*       orw = out + (size_t)row * DIM + colB;
            #pragma unroll
            for (int nt = 0; nt < 4; ++nt) {
                const __half2 xh2 = *reinterpret_cast<const __half2*>(xr + nt * 8);
                const float2 xv = __half22float2(xh2);
                const float d0 = acc[mt][nt][h * 2 + 0];
                const float d1 = acc[mt][nt][h * 2 + 1];
                const float o0 = fmaxf(one_mb + d0, 0.0f);
                const float o1 = fmaxf(one_mb + d1, 0.0f);
                const float r0 = fmaxf(1.0f - (br2[nt].x - (xv.x + o0)), 0.0f);
                const float r1 = fmaxf(1.0f - (br2[nt].y - (xv.y + o1)), 0.0f);
                __stcs(reinterpret_cast<float2*>(orw + nt * 8), make_float2(r0, r1));
            }
        }
    }
}

// ------------------------------------------------------------------ host side
typedef CUresult (*EncodeTiledFn)(CUtensorMap*, CUtensorMapDataType, cuuint32_t, void*,
                                  const cuuint64_t*, const cuuint64_t*, const cuuint32_t*,
                                  const cuuint32_t*, CUtensorMapInterleave, CUtensorMapSwizzle,
                                  CUtensorMapL2promotion, CUtensorMapFloatOOBfill);

static void make_map(EncodeTiledFn enc, CUtensorMap* m, void* ptr) {
    cuuint64_t dims[2]    = {DIM, DIM};
    cuuint64_t strides[1] = {(cuuint64_t)DIM * 2};
    cuuint32_t box[2]     = {BK, 128};
    cuuint32_t es[2]      = {1, 1};
    enc(m, CU_TENSOR_MAP_DATA_TYPE_FLOAT16, 2, ptr, dims, strides, box, es,
        CU_TENSOR_MAP_INTERLEAVE_NONE, CU_TENSOR_MAP_SWIZZLE_128B,
        CU_TENSOR_MAP_L2_PROMOTION_L2_256B, CU_TENSOR_MAP_FLOAT_OOB_FILL_NONE);
}

extern "C" void kernel_launch(void* const* d_in, const int* in_sizes, int n_in,
                              void* d_out, int out_size)
{
    const float* X        = (const float*)d_in[0];
    const float* W        = (const float*)d_in[1];
    const float* beta     = (const float*)d_in[2];
    const float* beta_res = (const float*)d_in[3];
    float* out            = (float*)d_out;

    void *pXh = nullptr, *pWh = nullptr;
    cudaGetSymbolAddress(&pXh, g_Xh);
    cudaGetSymbolAddress(&pWh, g_Wh);

    dim3 pgrid(DIM * DIM / (256 * 8), 2);
    to_half2_kernel<<<pgrid, 256>>>(X, W, (__half*)pXh, (__half*)pWh);

    void* encp = nullptr;
    cudaDriverEntryPointQueryResult st;
    cudaGetDriverEntryPointByVersion("cuTensorMapEncodeTiled", &encp, 12000,
                                     cudaEnableDefault, &st);
    EncodeTiledFn enc = (EncodeTiledFn)encp;

    static CUtensorMap mapA, mapB;
    make_map(enc, &mapA, pXh);
    make_map(enc, &mapB, pWh);

    cudaFuncSetAttribute(resfc_mma_f16_v11,
                         cudaFuncAttributeMaxDynamicSharedMemorySize, SMEM_TOTAL);
    dim3 grid(DIM / BN, DIM / BM);
    resfc_mma_f16_v11<<<grid, NT, SMEM_TOTAL>>>(mapA, mapB, (const __half*)pXh,
                                                beta, beta_res, out);
}